// round 10
// baseline (speedup 1.0000x reference)
#include <cuda_runtime.h>
#include <cuda_bf16.h>
#include <math.h>

// ---------------- problem constants ----------------
#define BATCH      16
#define SEQ        2048
#define NTOK       (BATCH*SEQ)          // 32768
#define INPUT_DIM  1024
#define HIDDEN     256
#define D_STATE    32
#define D_INNER    512
#define NHEADS     16
#define HEADDIM    32
#define CONV_DIM   576
#define D_IN_PROJ  1104
#define KCONV      4
#define EPS        1e-5f
#define CHUNK      128
#define NCH        (SEQ/CHUNK)          // 16

// ---------------- scratch (device globals) ----------
__device__ __align__(128) float g_act [NTOK*HIDDEN];
__device__ __align__(128) float g_z   [NTOK*D_IN_PROJ];
__device__ __align__(128) float g_xbc [NTOK*CONV_DIM];
__device__ __align__(128) float g_dt  [NTOK*NHEADS];
__device__ __align__(128) float g_dA  [NTOK*NHEADS];
__device__ __align__(128) float g_y   [NTOK*D_INNER];
__device__ __align__(128) float g_o   [NTOK*HIDDEN];
__device__ __align__(128) float g_cum [NTOK*NHEADS];
__device__ __align__(128) float g_F   [BATCH*NHEADS*NCH*32*32];
__device__ __align__(128) float g_Hin [BATCH*NHEADS*NCH*32*32];

// bf16 hi/lo planes
__device__ __align__(128) __nv_bfloat16 g_xhi [NTOK*INPUT_DIM];
__device__ __align__(128) __nv_bfloat16 g_xlo [NTOK*INPUT_DIM];
__device__ __align__(128) __nv_bfloat16 g_ahi [NTOK*HIDDEN];
__device__ __align__(128) __nv_bfloat16 g_alo [NTOK*HIDDEN];
__device__ __align__(128) __nv_bfloat16 g_yhi [NTOK*D_INNER];
__device__ __align__(128) __nv_bfloat16 g_ylo [NTOK*D_INNER];
__device__ __align__(128) __nv_bfloat16 g_lhi [NTOK*HIDDEN];
__device__ __align__(128) __nv_bfloat16 g_llo [NTOK*HIDDEN];
__device__ __align__(128) __nv_bfloat16 g_whi [1351680];
__device__ __align__(128) __nv_bfloat16 g_wlo [1351680];

// offsets into g_whi/g_wlo (transposed [N][K] layout)
#define OFF_IPW  0
#define OFF_INW  262144
#define OFF_OUTW 827392
#define OFF_W1   1089536
#define OFF_W2   1220608

// ---------------- helpers ----------------
__device__ __forceinline__ float blockSum(float v) {
    __shared__ float sh[8];
    __shared__ float total;
    int lane = threadIdx.x & 31, wid = threadIdx.x >> 5;
    #pragma unroll
    for (int o = 16; o > 0; o >>= 1) v += __shfl_xor_sync(0xffffffffu, v, o);
    if (lane == 0) sh[wid] = v;
    __syncthreads();
    if (threadIdx.x == 0) {
        float t = 0.f;
        int nw = (int)(blockDim.x >> 5);
        for (int i = 0; i < nw; i++) t += sh[i];
        total = t;
    }
    __syncthreads();
    return total;
}

__device__ __forceinline__ float siluf(float x) { return x / (1.f + expf(-x)); }

__device__ __forceinline__ void cp_async16(unsigned saddr, const void* gaddr) {
    asm volatile("cp.async.cg.shared.global [%0], [%1], 16;\n"
                 :: "r"(saddr), "l"(gaddr));
}
__device__ __forceinline__ void cp_async16_pred(unsigned saddr, const void* gaddr, int srcsz) {
    asm volatile("cp.async.cg.shared.global [%0], [%1], 16, %2;\n"
                 :: "r"(saddr), "l"(gaddr), "r"(srcsz));
}
__device__ __forceinline__ void cp_commit() { asm volatile("cp.async.commit_group;\n"); }
__device__ __forceinline__ void cp_wait1()  { asm volatile("cp.async.wait_group 1;\n"); }

__device__ __forceinline__ void split_pair(float a, float b,
                                           __nv_bfloat16* hi, __nv_bfloat16* lo,
                                           size_t off) {
    __nv_bfloat16 ha = __float2bfloat16(a), hb = __float2bfloat16(b);
    __nv_bfloat162 h; h.x = ha; h.y = hb;
    __nv_bfloat162 l;
    l.x = __float2bfloat16(a - __bfloat162float(ha));
    l.y = __float2bfloat16(b - __bfloat162float(hb));
    *reinterpret_cast<__nv_bfloat162*>(hi + off) = h;
    *reinterpret_cast<__nv_bfloat162*>(lo + off) = l;
}

// ---------------- bf16x3 tensor-core GEMM -----------------------------------
// C[M,N] = A[M,K] @ W[N,K]^T + bias via mma.m16n8k16.bf16, split-3 products.
// Block 128x128x16, 128 threads = 4 warps (2x2), warp tile 64x64, 3-stage
// cp.async. Smem per plane: [128 rows][12 u32] (24 bf16 cap, 8 used + pad;
// banks gid*12+tig all distinct -> conflict-free fragment loads).
// MODE 0: C fp32.  MODE 1: gelu -> planes.  MODE 2: C fp32 + planes.
#define PL_U32  (128*12)          // 1536 u32 per plane
#define STG_U32 (4*PL_U32)        // 6144 u32 per stage (Ahi,Alo,Bhi,Blo)
#define SMB_GEMM (3*STG_U32*4)    // 73728 bytes

template<int MODE>
__global__ void __launch_bounds__(128)
bgemm_kernel(const __nv_bfloat16* __restrict__ Ahi, const __nv_bfloat16* __restrict__ Alo,
             const __nv_bfloat16* __restrict__ Whi, const __nv_bfloat16* __restrict__ Wlo,
             const float* __restrict__ bias, float* __restrict__ C,
             __nv_bfloat16* __restrict__ Chi, __nv_bfloat16* __restrict__ Clo,
             int M, int N, int K)
{
    extern __shared__ unsigned smu[];
    int tid = threadIdx.x, lane = tid & 31, warp = tid >> 5;
    int wm = warp >> 1, wn = warp & 1;        // 2x2 warps, 64x64 each
    int gid = lane >> 2, tig = lane & 3;
    int row0 = blockIdx.y * 128, col0 = blockIdx.x * 128;

    int ac = tid & 1;       // 16B chunk within 32B row-slab
    int ar = tid >> 1;      // rows ar, ar+64

    unsigned smbase = (unsigned)__cvta_generic_to_shared(smu);

    float acc[4][8][4];
    #pragma unroll
    for (int i = 0; i < 4; i++)
        #pragma unroll
        for (int j = 0; j < 8; j++)
            #pragma unroll
            for (int q = 0; q < 4; q++) acc[i][j][q] = 0.f;

    int nB0 = col0 + ar, nB1 = col0 + ar + 64;
    int szB0 = (nB0 < N) ? 16 : 0, szB1 = (nB1 < N) ? 16 : 0;

    int nkt = K >> 4;

    // loader: one tile (stage s, k-offset kt)
    auto load_tile = [&](int s, int kt) {
        unsigned sb = smbase + (unsigned)(s * STG_U32) * 4;
        // A planes
        #pragma unroll
        for (int p = 0; p < 2; p++) {
            const __nv_bfloat16* Ap = p ? Alo : Ahi;
            unsigned pb = sb + (unsigned)(p * PL_U32) * 4;
            cp_async16(pb + (unsigned)(ar * 12 + ac * 4) * 4,
                       Ap + (size_t)(row0 + ar) * K + kt + ac * 8);
            cp_async16(pb + (unsigned)((ar + 64) * 12 + ac * 4) * 4,
                       Ap + (size_t)(row0 + ar + 64) * K + kt + ac * 8);
        }
        // B planes
        #pragma unroll
        for (int p = 0; p < 2; p++) {
            const __nv_bfloat16* Bp = p ? Wlo : Whi;
            unsigned pb = sb + (unsigned)((2 + p) * PL_U32) * 4;
            cp_async16_pred(pb + (unsigned)(ar * 12 + ac * 4) * 4,
                            Bp + (size_t)nB0 * K + kt + ac * 8, szB0);
            cp_async16_pred(pb + (unsigned)((ar + 64) * 12 + ac * 4) * 4,
                            Bp + (size_t)nB1 * K + kt + ac * 8, szB1);
        }
        cp_commit();
    };

    // prologue: stages 0,1
    load_tile(0, 0);
    if (nkt > 1) load_tile(1, 16); else cp_commit();

    for (int t = 0; t < nkt; t++) {
        cp_wait1();
        __syncthreads();

        if (t + 2 < nkt) load_tile((t + 2) % 3, (t + 2) << 4);
        else cp_commit();

        const unsigned* S   = smu + (t % 3) * STG_U32;
        const unsigned* SAh = S;
        const unsigned* SAl = S + PL_U32;
        const unsigned* SBh = S + 2 * PL_U32;
        const unsigned* SBl = S + 3 * PL_U32;

        unsigned ah[4][4], al[4][4];
        #pragma unroll
        for (int im = 0; im < 4; im++) {
            int rb = (wm * 64 + im * 16 + gid) * 12 + tig;
            ah[im][0] = SAh[rb];      ah[im][1] = SAh[rb + 96];
            ah[im][2] = SAh[rb + 4];  ah[im][3] = SAh[rb + 100];
            al[im][0] = SAl[rb];      al[im][1] = SAl[rb + 96];
            al[im][2] = SAl[rb + 4];  al[im][3] = SAl[rb + 100];
        }
        #pragma unroll
        for (int jn = 0; jn < 8; jn++) {
            int nb = (wn * 64 + jn * 8 + gid) * 12 + tig;
            unsigned bh0 = SBh[nb], bh1 = SBh[nb + 4];
            unsigned bl0 = SBl[nb], bl1 = SBl[nb + 4];
            #pragma unroll
            for (int im = 0; im < 4; im++) {
                asm volatile(
                    "mma.sync.aligned.m16n8k16.row.col.f32.bf16.bf16.f32 "
                    "{%0,%1,%2,%3}, {%4,%5,%6,%7}, {%8,%9}, {%0,%1,%2,%3};"
                    : "+f"(acc[im][jn][0]), "+f"(acc[im][jn][1]),
                      "+f"(acc[im][jn][2]), "+f"(acc[im][jn][3])
                    : "r"(ah[im][0]), "r"(ah[im][1]), "r"(ah[im][2]), "r"(ah[im][3]),
                      "r"(bh0), "r"(bh1));
                asm volatile(
                    "mma.sync.aligned.m16n8k16.row.col.f32.bf16.bf16.f32 "
                    "{%0,%1,%2,%3}, {%4,%5,%6,%7}, {%8,%9}, {%0,%1,%2,%3};"
                    : "+f"(acc[im][jn][0]), "+f"(acc[im][jn][1]),
                      "+f"(acc[im][jn][2]), "+f"(acc[im][jn][3])
                    : "r"(ah[im][0]), "r"(ah[im][1]), "r"(ah[im][2]), "r"(ah[im][3]),
                      "r"(bl0), "r"(bl1));
                asm volatile(
                    "mma.sync.aligned.m16n8k16.row.col.f32.bf16.bf16.f32 "
                    "{%0,%1,%2,%3}, {%4,%5,%6,%7}, {%8,%9}, {%0,%1,%2,%3};"
                    : "+f"(acc[im][jn][0]), "+f"(acc[im][jn][1]),
                      "+f"(acc[im][jn][2]), "+f"(acc[im][jn][3])
                    : "r"(al[im][0]), "r"(al[im][1]), "r"(al[im][2]), "r"(al[im][3]),
                      "r"(bh0), "r"(bh1));
            }
        }
    }

    // epilogue
    #pragma unroll
    for (int im = 0; im < 4; im++) {
        #pragma unroll
        for (int jn = 0; jn < 8; jn++) {
            int col = col0 + wn * 64 + jn * 8 + tig * 2;
            if (col >= N) continue;
            float b0 = bias[col], b1 = bias[col + 1];
            int r0 = row0 + wm * 64 + im * 16 + gid;
            float v0 = acc[im][jn][0] + b0;
            float v1 = acc[im][jn][1] + b1;
            float v2 = acc[im][jn][2] + b0;
            float v3 = acc[im][jn][3] + b1;
            if (MODE == 1) {
                v0 = 0.5f*v0*(1.f + erff(v0*0.70710678118654752f));
                v1 = 0.5f*v1*(1.f + erff(v1*0.70710678118654752f));
                v2 = 0.5f*v2*(1.f + erff(v2*0.70710678118654752f));
                v3 = 0.5f*v3*(1.f + erff(v3*0.70710678118654752f));
            }
            if (MODE == 0 || MODE == 2) {
                *reinterpret_cast<float2*>(&C[(size_t)r0 * N + col]) = make_float2(v0, v1);
                *reinterpret_cast<float2*>(&C[(size_t)(r0+8) * N + col]) = make_float2(v2, v3);
            }
            if (MODE == 1 || MODE == 2) {
                split_pair(v0, v1, Chi, Clo, (size_t)r0 * N + col);
                split_pair(v2, v3, Chi, Clo, (size_t)(r0+8) * N + col);
            }
        }
    }
}

// ---------------- preprocessing -------------------------------------------
__global__ void split_kernel(const float* __restrict__ src,
                             __nv_bfloat16* __restrict__ hi,
                             __nv_bfloat16* __restrict__ lo, int n2)
{
    int i = blockIdx.x * blockDim.x + threadIdx.x;
    if (i < n2) {
        float2 v = reinterpret_cast<const float2*>(src)[i];
        split_pair(v.x, v.y, hi, lo, (size_t)i * 2);
    }
}

// weight split + transpose: W[K][N] fp32 -> hi/lo [N][K] bf16
__global__ void wsplit_kernel(const float* __restrict__ W,
                              __nv_bfloat16* __restrict__ hi,
                              __nv_bfloat16* __restrict__ lo, int K, int N)
{
    int idx = blockIdx.x * blockDim.x + threadIdx.x;
    if (idx < N * K) {
        int n = idx / K, k = idx % K;
        float v = W[(size_t)k * N + n];
        __nv_bfloat16 h = __float2bfloat16(v);
        hi[idx] = h;
        lo[idx] = __float2bfloat16(v - __bfloat162float(h));
    }
}

// ---------------- conv (causal depthwise K=4) + silu + dt/dA ---------------
__global__ void conv_kernel(const float* __restrict__ z,
                            const float* __restrict__ convw,
                            const float* __restrict__ convb,
                            const float* __restrict__ dtb,
                            const float* __restrict__ Alog,
                            float* __restrict__ xbc,
                            float* __restrict__ dtO,
                            float* __restrict__ dAO)
{
    int tok = blockIdx.x;
    int b = tok >> 11, l = tok & 2047;
    for (int c = threadIdx.x; c < CONV_DIM + NHEADS; c += blockDim.x) {
        if (c < CONV_DIM) {
            float acc = convb[c];
            #pragma unroll
            for (int i = 0; i < KCONV; i++) {
                int ll = l - (KCONV - 1) + i;
                if (ll >= 0)
                    acc = fmaf(convw[c*KCONV + i],
                               z[(size_t)(b*SEQ + ll) * D_IN_PROJ + D_INNER + c], acc);
            }
            xbc[(size_t)tok * CONV_DIM + c] = siluf(acc);
        } else {
            int hh = c - CONV_DIM;
            float v = z[(size_t)tok * D_IN_PROJ + 2*D_INNER + 2*D_STATE + hh] + dtb[hh];
            float sp = (v > 20.f) ? v : log1pf(expf(v));
            dtO[tok*NHEADS + hh] = sp;
            dAO[tok*NHEADS + hh] = expf(-expf(Alog[hh]) * sp);
        }
    }
}

// ---------------- chunked selective scan: pass 1 (local scans) -------------
#define TT 32
__global__ void __launch_bounds__(128)
scan_local_kernel(const float* __restrict__ xbc, const float* __restrict__ dt,
                  const float* __restrict__ dA, const float* __restrict__ Dv,
                  float* __restrict__ y, float* __restrict__ cumO,
                  float* __restrict__ F)
{
    int hI = blockIdx.x;
    int b  = blockIdx.y;
    int ch = blockIdx.z;
    int lane = threadIdx.x & 31;
    int w    = threadIdx.x >> 5;
    float Dh = Dv[hI];

    float hs[8];
    #pragma unroll
    for (int i = 0; i < 8; i++) hs[i] = 0.f;
    float cum = 1.f;

    __shared__ float sB[TT][32];
    __shared__ float sC[TT][32];
    __shared__ float sdtx[TT][32];
    __shared__ float sxh[TT][32];
    __shared__ float sdA[TT];
    __shared__ float scum[TT];
    __shared__ float ypart[4][TT][32];

    int tchunk0 = b * SEQ + ch * CHUNK;

    for (int tile = 0; tile < CHUNK / TT; tile++) {
        int t0 = tchunk0 + tile * TT;
        for (int j = threadIdx.x; j < TT * 32; j += 128) {
            int tl = j >> 5, c = j & 31;
            int tok = t0 + tl;
            const float* row = xbc + (size_t)tok * CONV_DIM;
            sB[tl][c] = row[D_INNER + c];
            sC[tl][c] = row[D_INNER + D_STATE + c];
            float xv = row[hI * HEADDIM + c];
            sxh[tl][c]  = xv;
            sdtx[tl][c] = dt[tok * NHEADS + hI] * xv;
        }
        if (threadIdx.x < TT)
            sdA[threadIdx.x] = dA[(t0 + threadIdx.x) * NHEADS + hI];
        __syncthreads();

        for (int tl = 0; tl < TT; tl++) {
            float a  = sdA[tl];
            cum *= a;
            float dx = sdtx[tl][lane];
            float acc = 0.f;
            #pragma unroll
            for (int i = 0; i < 8; i++) {
                int n = w * 8 + i;
                hs[i] = fmaf(hs[i], a, dx * sB[tl][n]);
                acc   = fmaf(hs[i], sC[tl][n], acc);
            }
            ypart[w][tl][lane] = acc;
            if (threadIdx.x == 0) scum[tl] = cum;
        }
        __syncthreads();

        for (int j = threadIdx.x; j < TT * 32; j += 128) {
            int tl = j >> 5, p = j & 31;
            int tok = t0 + tl;
            float yv = ypart[0][tl][p] + ypart[1][tl][p] +
                       ypart[2][tl][p] + ypart[3][tl][p] + Dh * sxh[tl][p];
            y[(size_t)tok * D_INNER + hI * HEADDIM + p] = yv;
            if (p == 0) cumO[tok * NHEADS + hI] = scum[tl];
        }
        __syncthreads();
    }

    size_t fbase = (size_t)(((b * NHEADS + hI) * NCH + ch)) * 1024;
    #pragma unroll
    for (int i = 0; i < 8; i++) {
        int n = w * 8 + i;
        F[fbase + n * 32 + lane] = hs[i];
    }
}

// ---------------- pass 2: combine chunk states -----------------------------
__global__ void __launch_bounds__(256)
scan_combine_kernel(const float* __restrict__ F, const float* __restrict__ cum,
                    float* __restrict__ Hin)
{
    int hI = blockIdx.x, b = blockIdx.y;
    size_t base = (size_t)((b * NHEADS + hI) * NCH) * 1024;
    int off = threadIdx.x * 4;
    float4 hr = make_float4(0.f, 0.f, 0.f, 0.f);
    for (int c = 0; c < NCH; c++) {
        *reinterpret_cast<float4*>(&Hin[base + (size_t)c * 1024 + off]) = hr;
        float P = cum[(size_t)(b * SEQ + c * CHUNK + CHUNK - 1) * NHEADS + hI];
        float4 f = *reinterpret_cast<const float4*>(&F[base + (size_t)c * 1024 + off]);
        hr.x = fmaf(hr.x, P, f.x);
        hr.y = fmaf(hr.y, P, f.y);
        hr.z = fmaf(hr.z, P, f.z);
        hr.w = fmaf(hr.w, P, f.w);
    }
}

// ---------------- pass 3: apply chunk-initial-state correction -------------
__global__ void __launch_bounds__(128)
scan_fix_kernel(const float* __restrict__ xbc, const float* __restrict__ cum,
                const float* __restrict__ Hin, float* __restrict__ y)
{
    int hI = blockIdx.x, b = blockIdx.y, ch = blockIdx.z;
    if (ch == 0) return;
    int lane = threadIdx.x & 31, w = threadIdx.x >> 5;

    __shared__ float sh[32][32];
    size_t base = (size_t)(((b * NHEADS + hI) * NCH + ch)) * 1024;
    for (int j = threadIdx.x; j < 1024; j += 128)
        sh[j >> 5][j & 31] = Hin[base + j];
    __syncthreads();

    int t0 = b * SEQ + ch * CHUNK + w * 32;
    for (int tt = 0; tt < 32; tt++) {
        int tok = t0 + tt;
        float cv = xbc[(size_t)tok * CONV_DIM + D_INNER + D_STATE + lane];
        float pt = cum[tok * NHEADS + hI];
        float a0 = 0.f, a1 = 0.f;
        #pragma unroll
        for (int n = 0; n < 32; n += 2) {
            a0 = fmaf(__shfl_sync(0xffffffffu, cv, n),     sh[n][lane],     a0);
            a1 = fmaf(__shfl_sync(0xffffffffu, cv, n + 1), sh[n + 1][lane], a1);
        }
        y[(size_t)tok * D_INNER + hI * HEADDIM + lane] += pt * (a0 + a1);
    }
}

// ---------------- gated RMSNorm -> bf16 planes ------------------------------
__global__ void __launch_bounds__(256)
gatednorm_kernel(const float* __restrict__ y, const float* __restrict__ zx,
                 const float* __restrict__ nw,
                 __nv_bfloat16* __restrict__ yhi, __nv_bfloat16* __restrict__ ylo)
{
    int tok = blockIdx.x;
    int c0 = threadIdx.x * 2;
    float v0, v1, ss;
    {
        float z0 = zx[(size_t)tok * D_IN_PROJ + c0];
        float z1 = zx[(size_t)tok * D_IN_PROJ + c0 + 1];
        v0 = y[(size_t)tok * D_INNER + c0]     * siluf(z0);
        v1 = y[(size_t)tok * D_INNER + c0 + 1] * siluf(z1);
        ss = v0 * v0 + v1 * v1;
    }
    ss = blockSum(ss);
    float scale = rsqrtf(ss / (float)D_INNER + EPS);
    split_pair(v0 * scale * nw[c0], v1 * scale * nw[c0 + 1],
               yhi, ylo, (size_t)tok * D_INNER + c0);
}

// ---------------- residual + RMSNorm: act fp32 + planes ---------------------
__global__ void __launch_bounds__(256)
resnorm_kernel(const float* __restrict__ o, float* __restrict__ act,
               const float* __restrict__ wgt,
               __nv_bfloat16* __restrict__ ahi, __nv_bfloat16* __restrict__ alo)
{
    int tok = blockIdx.x, c = threadIdx.x;
    float v = o[(size_t)tok * HIDDEN + c] + act[(size_t)tok * HIDDEN + c];
    float ss = blockSum(v * v);
    float r = v * rsqrtf(ss / (float)HIDDEN + EPS) * wgt[c];
    act[(size_t)tok * HIDDEN + c] = r;
    __nv_bfloat16 h = __float2bfloat16(r);
    ahi[(size_t)tok * HIDDEN + c] = h;
    alo[(size_t)tok * HIDDEN + c] = __float2bfloat16(r - __bfloat162float(h));
}

// ---------------- LayerNorm variants ----------------------------------------
__global__ void __launch_bounds__(256)
layernorm_planes_kernel(const float* __restrict__ in, const float* __restrict__ w,
                        const float* __restrict__ bsl,
                        __nv_bfloat16* __restrict__ ohi, __nv_bfloat16* __restrict__ olo)
{
    int tok = blockIdx.x, c = threadIdx.x;
    float v = in[(size_t)tok * HIDDEN + c];
    float s  = blockSum(v);
    float s2 = blockSum(v * v);
    float m = s / (float)HIDDEN;
    float var = s2 / (float)HIDDEN - m * m;
    float r = (v - m) * rsqrtf(var + EPS) * w[c] + bsl[c];
    __nv_bfloat16 h = __float2bfloat16(r);
    ohi[(size_t)tok * HIDDEN + c] = h;
    olo[(size_t)tok * HIDDEN + c] = __float2bfloat16(r - __bfloat162float(h));
}

__global__ void __launch_bounds__(256)
layernorm_kernel(const float* __restrict__ in, const float* __restrict__ w,
                 const float* __restrict__ bsl, float* __restrict__ out)
{
    int tok = blockIdx.x, c = threadIdx.x;
    float v = in[(size_t)tok * HIDDEN + c];
    float s  = blockSum(v);
    float s2 = blockSum(v * v);
    float m = s / (float)HIDDEN;
    float var = s2 / (float)HIDDEN - m * m;
    out[(size_t)tok * HIDDEN + c] = (v - m) * rsqrtf(var + EPS) * w[c] + bsl[c];
}

// ---------------- launch ----------------------------------------------------
extern "C" void kernel_launch(void* const* d_in, const int* in_sizes, int n_in,
                              void* d_out, int out_size)
{
    const float* x      = (const float*)d_in[0];
    const float* ip_w   = (const float*)d_in[1];
    const float* ip_b   = (const float*)d_in[2];
    const float* m_inw  = (const float*)d_in[3];
    const float* m_inb  = (const float*)d_in[4];
    const float* m_convw= (const float*)d_in[5];
    const float* m_convb= (const float*)d_in[6];
    const float* m_dtb  = (const float*)d_in[7];
    const float* m_Alog = (const float*)d_in[8];
    const float* m_D    = (const float*)d_in[9];
    const float* m_nw   = (const float*)d_in[10];
    const float* m_outw = (const float*)d_in[11];
    const float* m_outb = (const float*)d_in[12];
    const float* rms_w  = (const float*)d_in[13];
    const float* ln1_w  = (const float*)d_in[14];
    const float* ln1_b  = (const float*)d_in[15];
    const float* w1     = (const float*)d_in[16];
    const float* b1     = (const float*)d_in[17];
    const float* w2     = (const float*)d_in[18];
    const float* b2     = (const float*)d_in[19];
    const float* ln2_w  = (const float*)d_in[20];
    const float* ln2_b  = (const float*)d_in[21];
    float* out = (float*)d_out;

    float *act, *z, *xbc, *dt, *dA, *y, *o, *cum, *F, *Hin;
    __nv_bfloat16 *xhi, *xlo, *ahi, *alo, *yhi, *ylo, *lhi, *llo, *whi, *wlo;
    cudaGetSymbolAddress((void**)&act, g_act);
    cudaGetSymbolAddress((void**)&z,   g_z);
    cudaGetSymbolAddress((void**)&xbc, g_xbc);
    cudaGetSymbolAddress((void**)&dt,  g_dt);
    cudaGetSymbolAddress((void**)&dA,  g_dA);
    cudaGetSymbolAddress((void**)&y,   g_y);
    cudaGetSymbolAddress((void**)&o,   g_o);
    cudaGetSymbolAddress((void**)&cum, g_cum);
    cudaGetSymbolAddress((void**)&F,   g_F);
    cudaGetSymbolAddress((void**)&Hin, g_Hin);
    cudaGetSymbolAddress((void**)&xhi, g_xhi);
    cudaGetSymbolAddress((void**)&xlo, g_xlo);
    cudaGetSymbolAddress((void**)&ahi, g_ahi);
    cudaGetSymbolAddress((void**)&alo, g_alo);
    cudaGetSymbolAddress((void**)&yhi, g_yhi);
    cudaGetSymbolAddress((void**)&ylo, g_ylo);
    cudaGetSymbolAddress((void**)&lhi, g_lhi);
    cudaGetSymbolAddress((void**)&llo, g_llo);
    cudaGetSymbolAddress((void**)&whi, g_whi);
    cudaGetSymbolAddress((void**)&wlo, g_wlo);

    cudaFuncSetAttribute(bgemm_kernel<0>, cudaFuncAttributeMaxDynamicSharedMemorySize, SMB_GEMM);
    cudaFuncSetAttribute(bgemm_kernel<1>, cudaFuncAttributeMaxDynamicSharedMemorySize, SMB_GEMM);
    cudaFuncSetAttribute(bgemm_kernel<2>, cudaFuncAttributeMaxDynamicSharedMemorySize, SMB_GEMM);

    // ---- preprocessing: split x + weights (transpose W to [N][K]) ----
    {
        int n2 = NTOK * INPUT_DIM / 2;
        split_kernel<<<(n2 + 255) / 256, 256>>>(x, xhi, xlo, n2);
        int n;
        n = 256 * 1024;
        wsplit_kernel<<<(n + 255) / 256, 256>>>(ip_w, whi + OFF_IPW, wlo + OFF_IPW, 1024, 256);
        n = 1104 * 256;
        wsplit_kernel<<<(n + 255) / 256, 256>>>(m_inw, whi + OFF_INW, wlo + OFF_INW, 256, 1104);
        wsplit_kernel<<<(n + 255) / 256, 256>>>(m_inw + 256 * 1104,
            whi + OFF_INW + 1104 * 256, wlo + OFF_INW + 1104 * 256, 256, 1104);
        n = 256 * 512;
        wsplit_kernel<<<(n + 255) / 256, 256>>>(m_outw, whi + OFF_OUTW, wlo + OFF_OUTW, 512, 256);
        wsplit_kernel<<<(n + 255) / 256, 256>>>(m_outw + 512 * 256,
            whi + OFF_OUTW + 256 * 512, wlo + OFF_OUTW + 256 * 512, 512, 256);
        n = 512 * 256;
        wsplit_kernel<<<(n + 255) / 256, 256>>>(w1, whi + OFF_W1, wlo + OFF_W1, 256, 512);
        wsplit_kernel<<<(n + 255) / 256, 256>>>(w2, whi + OFF_W2, wlo + OFF_W2, 512, 256);
    }

    const int MB = NTOK / 128;   // 256 row-blocks

    // input projection: act fp32 + planes
    bgemm_kernel<2><<<dim3(2, MB), 128, SMB_GEMM>>>(xhi, xlo,
        whi + OFF_IPW, wlo + OFF_IPW, ip_b, act, ahi, alo, NTOK, HIDDEN, INPUT_DIM);

    for (int i = 0; i < 2; i++) {
        bgemm_kernel<0><<<dim3(9, MB), 128, SMB_GEMM>>>(ahi, alo,
            whi + OFF_INW + (size_t)i * 1104 * 256, wlo + OFF_INW + (size_t)i * 1104 * 256,
            m_inb + i * D_IN_PROJ, z, (__nv_bfloat16*)nullptr, (__nv_bfloat16*)nullptr,
            NTOK, D_IN_PROJ, HIDDEN);
        conv_kernel<<<NTOK, 256>>>(z, m_convw + (size_t)i * CONV_DIM * KCONV,
                                   m_convb + i * CONV_DIM, m_dtb + i * NHEADS,
                                   m_Alog + i * NHEADS, xbc, dt, dA);
        scan_local_kernel<<<dim3(NHEADS, BATCH, NCH), 128>>>(
            xbc, dt, dA, m_D + i * NHEADS, y, cum, F);
        scan_combine_kernel<<<dim3(NHEADS, BATCH), 256>>>(F, cum, Hin);
        scan_fix_kernel<<<dim3(NHEADS, BATCH, NCH), 128>>>(xbc, cum, Hin, y);
        gatednorm_kernel<<<NTOK, 256>>>(y, z, m_nw + i * D_INNER, yhi, ylo);
        bgemm_kernel<0><<<dim3(2, MB), 128, SMB_GEMM>>>(yhi, ylo,
            whi + OFF_OUTW + (size_t)i * 256 * 512, wlo + OFF_OUTW + (size_t)i * 256 * 512,
            m_outb + i * HIDDEN, o, (__nv_bfloat16*)nullptr, (__nv_bfloat16*)nullptr,
            NTOK, HIDDEN, D_INNER);
        resnorm_kernel<<<NTOK, 256>>>(o, act, rms_w + i * HIDDEN, ahi, alo);
    }

    // MLP head
    layernorm_planes_kernel<<<NTOK, 256>>>(act, ln1_w, ln1_b, lhi, llo);
    bgemm_kernel<1><<<dim3(4, MB), 128, SMB_GEMM>>>(lhi, llo,
        whi + OFF_W1, wlo + OFF_W1, b1, (float*)nullptr, yhi, ylo,
        NTOK, 2 * HIDDEN, HIDDEN);   // gelu -> planes
    bgemm_kernel<0><<<dim3(2, MB), 128, SMB_GEMM>>>(yhi, ylo,
        whi + OFF_W2, wlo + OFF_W2, b2, o, (__nv_bfloat16*)nullptr, (__nv_bfloat16*)nullptr,
        NTOK, HIDDEN, 2 * HIDDEN);
    layernorm_kernel<<<NTOK, 256>>>(o, ln2_w, ln2_b, out);
}

// round 11
// speedup vs baseline: 1.1893x; 1.1893x over previous
#include <cuda_runtime.h>
#include <cuda_bf16.h>
#include <math.h>

// ---------------- problem constants ----------------
#define BATCH      16
#define SEQ        2048
#define NTOK       (BATCH*SEQ)          // 32768
#define INPUT_DIM  1024
#define HIDDEN     256
#define D_STATE    32
#define D_INNER    512
#define NHEADS     16
#define HEADDIM    32
#define CONV_DIM   576
#define D_IN_PROJ  1104
#define KCONV      4
#define EPS        1e-5f
#define CHUNK      128
#define NCH        (SEQ/CHUNK)          // 16

// ---------------- scratch (device globals) ----------
__device__ __align__(128) float g_act [NTOK*HIDDEN];
__device__ __align__(128) float g_z   [NTOK*D_IN_PROJ];
__device__ __align__(128) float g_xbc [NTOK*CONV_DIM];
__device__ __align__(128) float g_dt  [NTOK*NHEADS];
__device__ __align__(128) float g_dA  [NTOK*NHEADS];
__device__ __align__(128) float g_y   [NTOK*D_INNER];
__device__ __align__(128) float g_o   [NTOK*HIDDEN];
__device__ __align__(128) float g_cum [NTOK*NHEADS];
__device__ __align__(128) float g_F   [BATCH*NHEADS*NCH*32*32];
__device__ __align__(128) float g_Hin [BATCH*NHEADS*NCH*32*32];

// ---------------- helpers ----------------
__device__ __forceinline__ float blockSum(float v) {
    __shared__ float sh[8];
    __shared__ float total;
    int lane = threadIdx.x & 31, wid = threadIdx.x >> 5;
    #pragma unroll
    for (int o = 16; o > 0; o >>= 1) v += __shfl_xor_sync(0xffffffffu, v, o);
    if (lane == 0) sh[wid] = v;
    __syncthreads();
    if (threadIdx.x == 0) {
        float t = 0.f;
        int nw = (int)(blockDim.x >> 5);
        for (int i = 0; i < nw; i++) t += sh[i];
        total = t;
    }
    __syncthreads();
    return total;
}

__device__ __forceinline__ float siluf(float x) { return x / (1.f + expf(-x)); }

__device__ __forceinline__ unsigned f2tf(float x) {
    unsigned r;
    asm("cvt.rna.tf32.f32 %0, %1;" : "=r"(r) : "f"(x));
    return r;
}

__device__ __forceinline__ void cp_async16(unsigned saddr, const void* gaddr) {
    asm volatile("cp.async.cg.shared.global [%0], [%1], 16;\n"
                 :: "r"(saddr), "l"(gaddr));
}
__device__ __forceinline__ void cp_async16_pred(unsigned saddr, const void* gaddr, int srcsz) {
    asm volatile("cp.async.cg.shared.global [%0], [%1], 16, %2;\n"
                 :: "r"(saddr), "l"(gaddr), "r"(srcsz));
}
__device__ __forceinline__ void cp_commit() { asm volatile("cp.async.commit_group;\n"); }
__device__ __forceinline__ void cp_wait1()  { asm volatile("cp.async.wait_group 1;\n"); }

// ---------------- TF32 tensor-core GEMM (FROZEN from round 9) ---------------
// Block 128x128x16, 128 threads = 4 warps (2x2), warp tile 64x64, 3-stage
// cp.async pipeline. tf32 conversion at fragment load (cvt.rna).
// MODE 0: C = A@W + bias.  MODE 1: gelu epilogue.
#define ASTR 20
#define BSTR 136
#define A_STG (128*ASTR)               // 2560 floats
#define B_STG (16*BSTR)                // 2176 floats
#define B_BASE (3*A_STG)               // 7680
#define SM_FLOATS (3*A_STG + 3*B_STG)  // 14208 floats = 56832 B

template<int MODE>
__global__ void __launch_bounds__(128)
tgemm_kernel(const float* __restrict__ A, const float* __restrict__ W,
             const float* __restrict__ bias, float* __restrict__ C,
             int M, int N, int K)
{
    extern __shared__ float sm[];
    int tid = threadIdx.x, lane = tid & 31, warp = tid >> 5;
    int wm = warp >> 1, wn = warp & 1;       // 2x2 warps, 64x64 each
    int gid = lane >> 2, tig = lane & 3;
    int row0 = blockIdx.y * 128, col0 = blockIdx.x * 128;

    int akq = tid & 3,  arb = tid >> 2;      // A: rows arb+p*32, float4 col akq
    int bnq = tid & 31, bkr = tid >> 5;      // B: rows bkr+p*4,  float4 col bnq

    const float* Abase = A + (size_t)row0 * K;
    int bcol = col0 + bnq * 4;
    int bsz  = (bcol < N) ? 16 : 0;

    float acc[4][8][4];
    #pragma unroll
    for (int i = 0; i < 4; i++)
        #pragma unroll
        for (int j = 0; j < 8; j++)
            #pragma unroll
            for (int q = 0; q < 4; q++) acc[i][j][q] = 0.f;

    unsigned smbase = (unsigned)__cvta_generic_to_shared(sm);
    int nkt = K >> 4;

    // prologue: stages 0,1
    #pragma unroll
    for (int s = 0; s < 2; s++) {
        if (s < nkt) {
            int kt = s << 4;
            #pragma unroll
            for (int p = 0; p < 4; p++)
                cp_async16(smbase + (s*A_STG + (arb + p*32)*ASTR + akq*4)*4,
                           &Abase[(size_t)(arb + p*32) * K + kt + akq*4]);
            #pragma unroll
            for (int p = 0; p < 4; p++)
                cp_async16_pred(smbase + (B_BASE + s*B_STG + (bkr + p*4)*BSTR + bnq*4)*4,
                                &W[(size_t)(kt + bkr + p*4) * N + bcol], bsz);
        }
        cp_commit();
    }

    for (int t = 0; t < nkt; t++) {
        cp_wait1();
        __syncthreads();

        // prefetch stage t+2
        {
            int tn = t + 2;
            if (tn < nkt) {
                int s = tn % 3;
                int kt = tn << 4;
                #pragma unroll
                for (int p = 0; p < 4; p++)
                    cp_async16(smbase + (s*A_STG + (arb + p*32)*ASTR + akq*4)*4,
                               &Abase[(size_t)(arb + p*32) * K + kt + akq*4]);
                #pragma unroll
                for (int p = 0; p < 4; p++)
                    cp_async16_pred(smbase + (B_BASE + s*B_STG + (bkr + p*4)*BSTR + bnq*4)*4,
                                    &W[(size_t)(kt + bkr + p*4) * N + bcol], bsz);
            }
            cp_commit();
        }

        const float* As = sm + (t % 3) * A_STG;
        const float* Bs = sm + B_BASE + (t % 3) * B_STG;

        #pragma unroll
        for (int kc = 0; kc < 2; kc++) {
            unsigned af[4][4], bf[8][2];
            #pragma unroll
            for (int im = 0; im < 4; im++) {
                const float* base = &As[(wm*64 + im*16 + gid)*ASTR + kc*8 + tig];
                af[im][0] = f2tf(base[0]);
                af[im][1] = f2tf(base[8*ASTR]);
                af[im][2] = f2tf(base[4]);
                af[im][3] = f2tf(base[8*ASTR + 4]);
            }
            #pragma unroll
            for (int jn = 0; jn < 8; jn++) {
                int cb = wn*64 + jn*8 + gid;
                bf[jn][0] = f2tf(Bs[(kc*8 + tig    )*BSTR + cb]);
                bf[jn][1] = f2tf(Bs[(kc*8 + tig + 4)*BSTR + cb]);
            }
            #pragma unroll
            for (int im = 0; im < 4; im++)
                #pragma unroll
                for (int jn = 0; jn < 8; jn++) {
                    asm volatile(
                        "mma.sync.aligned.m16n8k8.row.col.f32.tf32.tf32.f32 "
                        "{%0,%1,%2,%3}, {%4,%5,%6,%7}, {%8,%9}, {%0,%1,%2,%3};"
                        : "+f"(acc[im][jn][0]), "+f"(acc[im][jn][1]),
                          "+f"(acc[im][jn][2]), "+f"(acc[im][jn][3])
                        : "r"(af[im][0]), "r"(af[im][1]),
                          "r"(af[im][2]), "r"(af[im][3]),
                          "r"(bf[jn][0]), "r"(bf[jn][1]));
                }
        }
    }

    // epilogue
    #pragma unroll
    for (int im = 0; im < 4; im++) {
        #pragma unroll
        for (int jn = 0; jn < 8; jn++) {
            int col = col0 + wn*64 + jn*8 + tig*2;
            if (col >= N) continue;
            float b0 = bias[col], b1 = bias[col + 1];
            int r0 = row0 + wm*64 + im*16 + gid;
            float v0 = acc[im][jn][0] + b0;
            float v1 = acc[im][jn][1] + b1;
            float v2 = acc[im][jn][2] + b0;
            float v3 = acc[im][jn][3] + b1;
            if (MODE == 1) {
                v0 = 0.5f*v0*(1.f + erff(v0*0.70710678118654752f));
                v1 = 0.5f*v1*(1.f + erff(v1*0.70710678118654752f));
                v2 = 0.5f*v2*(1.f + erff(v2*0.70710678118654752f));
                v3 = 0.5f*v3*(1.f + erff(v3*0.70710678118654752f));
            }
            *reinterpret_cast<float2*>(&C[(size_t)r0 * N + col]) = make_float2(v0, v1);
            *reinterpret_cast<float2*>(&C[(size_t)(r0+8) * N + col]) = make_float2(v2, v3);
        }
    }
}

// ---------------- conv v2: channel-major, rolling window --------------------
// thread = (channel c, strip of 32 tokens). Coalesced across channels.
// Same fma order as v1 (i = 0..3), zero-padded terms via fmaf(w,0,acc) which
// is bit-exact vs skipping -> numerics identical to round-9 conv.
#define CTOK 32
__global__ void __launch_bounds__(128)
conv_kernel(const float* __restrict__ z,
            const float* __restrict__ convw,
            const float* __restrict__ convb,
            const float* __restrict__ dtb,
            const float* __restrict__ Alog,
            float* __restrict__ xbc,
            float* __restrict__ dtO,
            float* __restrict__ dAO)
{
    int c = blockIdx.x * 128 + threadIdx.x;
    int tok0 = blockIdx.y * CTOK;
    int l0 = tok0 & (SEQ - 1);

    if (c < CONV_DIM) {
        float w0 = convw[c*KCONV + 0];
        float w1 = convw[c*KCONV + 1];
        float w2 = convw[c*KCONV + 2];
        float w3 = convw[c*KCONV + 3];
        float bv = convb[c];
        const float* zp = z + (size_t)tok0 * D_IN_PROJ + D_INNER + c;
        // l0 is a multiple of 32, so l0 > 0 implies l0 >= 32 >= 3
        float xm3 = (l0 > 0) ? zp[-3 * D_IN_PROJ] : 0.f;
        float xm2 = (l0 > 0) ? zp[-2 * D_IN_PROJ] : 0.f;
        float xm1 = (l0 > 0) ? zp[-1 * D_IN_PROJ] : 0.f;
        float* xp = xbc + (size_t)tok0 * CONV_DIM + c;
        #pragma unroll 4
        for (int t = 0; t < CTOK; t++) {
            float x0 = zp[(size_t)t * D_IN_PROJ];
            float acc = bv;
            acc = fmaf(w0, xm3, acc);
            acc = fmaf(w1, xm2, acc);
            acc = fmaf(w2, xm1, acc);
            acc = fmaf(w3, x0,  acc);
            xp[(size_t)t * CONV_DIM] = siluf(acc);
            xm3 = xm2; xm2 = xm1; xm1 = x0;
        }
    } else if (c < CONV_DIM + NHEADS) {
        int hh = c - CONV_DIM;
        float db = dtb[hh];
        float nA = -expf(Alog[hh]);
        const float* zp = z + (size_t)tok0 * D_IN_PROJ + 2*D_INNER + 2*D_STATE + hh;
        #pragma unroll 4
        for (int t = 0; t < CTOK; t++) {
            float v = zp[(size_t)t * D_IN_PROJ] + db;
            float sp = (v > 20.f) ? v : log1pf(expf(v));
            int tok = tok0 + t;
            dtO[tok*NHEADS + hh] = sp;
            dAO[tok*NHEADS + hh] = expf(nA * sp);
        }
    }
}

// ---------------- chunked selective scan: pass 1 (local scans) -------------
#define TT 32
__global__ void __launch_bounds__(128, 8)
scan_local_kernel(const float* __restrict__ xbc, const float* __restrict__ dt,
                  const float* __restrict__ dA, const float* __restrict__ Dv,
                  float* __restrict__ y, float* __restrict__ cumO,
                  float* __restrict__ F)
{
    int hI = blockIdx.x;
    int b  = blockIdx.y;
    int ch = blockIdx.z;
    int lane = threadIdx.x & 31;
    int w    = threadIdx.x >> 5;
    float Dh = Dv[hI];

    float hs[8];
    #pragma unroll
    for (int i = 0; i < 8; i++) hs[i] = 0.f;
    float cum = 1.f;

    __shared__ float sB[TT][32];
    __shared__ float sC[TT][32];
    __shared__ float sdtx[TT][32];
    __shared__ float sxh[TT][32];
    __shared__ float sdA[TT];
    __shared__ float scum[TT];
    __shared__ float ypart[4][TT][32];

    int tchunk0 = b * SEQ + ch * CHUNK;

    for (int tile = 0; tile < CHUNK / TT; tile++) {
        int t0 = tchunk0 + tile * TT;
        for (int j = threadIdx.x; j < TT * 32; j += 128) {
            int tl = j >> 5, c = j & 31;
            int tok = t0 + tl;
            const float* row = xbc + (size_t)tok * CONV_DIM;
            sB[tl][c] = row[D_INNER + c];
            sC[tl][c] = row[D_INNER + D_STATE + c];
            float xv = row[hI * HEADDIM + c];
            sxh[tl][c]  = xv;
            sdtx[tl][c] = dt[tok * NHEADS + hI] * xv;
        }
        if (threadIdx.x < TT)
            sdA[threadIdx.x] = dA[(t0 + threadIdx.x) * NHEADS + hI];
        __syncthreads();

        for (int tl = 0; tl < TT; tl++) {
            float a  = sdA[tl];
            cum *= a;
            float dx = sdtx[tl][lane];
            float acc = 0.f;
            #pragma unroll
            for (int i = 0; i < 8; i++) {
                int n = w * 8 + i;
                hs[i] = fmaf(hs[i], a, dx * sB[tl][n]);
                acc   = fmaf(hs[i], sC[tl][n], acc);
            }
            ypart[w][tl][lane] = acc;
            if (threadIdx.x == 0) scum[tl] = cum;
        }
        __syncthreads();

        for (int j = threadIdx.x; j < TT * 32; j += 128) {
            int tl = j >> 5, p = j & 31;
            int tok = t0 + tl;
            float yv = ypart[0][tl][p] + ypart[1][tl][p] +
                       ypart[2][tl][p] + ypart[3][tl][p] + Dh * sxh[tl][p];
            y[(size_t)tok * D_INNER + hI * HEADDIM + p] = yv;
            if (p == 0) cumO[tok * NHEADS + hI] = scum[tl];
        }
        __syncthreads();
    }

    size_t fbase = (size_t)(((b * NHEADS + hI) * NCH + ch)) * 1024;
    #pragma unroll
    for (int i = 0; i < 8; i++) {
        int n = w * 8 + i;
        F[fbase + n * 32 + lane] = hs[i];
    }
}

// ---------------- pass 2: combine chunk states -----------------------------
__global__ void __launch_bounds__(256)
scan_combine_kernel(const float* __restrict__ F, const float* __restrict__ cum,
                    float* __restrict__ Hin)
{
    int hI = blockIdx.x, b = blockIdx.y;
    size_t base = (size_t)((b * NHEADS + hI) * NCH) * 1024;
    int off = threadIdx.x * 4;
    float4 hr = make_float4(0.f, 0.f, 0.f, 0.f);
    for (int c = 0; c < NCH; c++) {
        *reinterpret_cast<float4*>(&Hin[base + (size_t)c * 1024 + off]) = hr;
        float P = cum[(size_t)(b * SEQ + c * CHUNK + CHUNK - 1) * NHEADS + hI];
        float4 f = *reinterpret_cast<const float4*>(&F[base + (size_t)c * 1024 + off]);
        hr.x = fmaf(hr.x, P, f.x);
        hr.y = fmaf(hr.y, P, f.y);
        hr.z = fmaf(hr.z, P, f.z);
        hr.w = fmaf(hr.w, P, f.w);
    }
}

// ---------------- pass 3: apply chunk-initial-state correction -------------
__global__ void __launch_bounds__(128)
scan_fix_kernel(const float* __restrict__ xbc, const float* __restrict__ cum,
                const float* __restrict__ Hin, float* __restrict__ y)
{
    int hI = blockIdx.x, b = blockIdx.y, ch = blockIdx.z;
    if (ch == 0) return;
    int lane = threadIdx.x & 31, w = threadIdx.x >> 5;

    __shared__ float sh[32][32];
    size_t base = (size_t)(((b * NHEADS + hI) * NCH + ch)) * 1024;
    for (int j = threadIdx.x; j < 1024; j += 128)
        sh[j >> 5][j & 31] = Hin[base + j];
    __syncthreads();

    int t0 = b * SEQ + ch * CHUNK + w * 32;
    for (int tt = 0; tt < 32; tt++) {
        int tok = t0 + tt;
        float cv = xbc[(size_t)tok * CONV_DIM + D_INNER + D_STATE + lane];
        float pt = cum[tok * NHEADS + hI];
        float a0 = 0.f, a1 = 0.f;
        #pragma unroll
        for (int n = 0; n < 32; n += 2) {
            a0 = fmaf(__shfl_sync(0xffffffffu, cv, n),     sh[n][lane],     a0);
            a1 = fmaf(__shfl_sync(0xffffffffu, cv, n + 1), sh[n + 1][lane], a1);
        }
        y[(size_t)tok * D_INNER + hI * HEADDIM + lane] += pt * (a0 + a1);
    }
}

// ---------------- gated RMSNorm --------------------------------------------
__global__ void __launch_bounds__(256)
gatednorm_kernel(float* __restrict__ y, const float* __restrict__ zx,
                 const float* __restrict__ nw)
{
    int tok = blockIdx.x;
    float v[2]; float ss = 0.f;
    #pragma unroll
    for (int r = 0; r < 2; r++) {
        int c = threadIdx.x + r * 256;
        float zv = zx[(size_t)tok * D_IN_PROJ + c];
        float yv = y[(size_t)tok * D_INNER + c];
        v[r] = yv * siluf(zv);
        ss += v[r] * v[r];
    }
    ss = blockSum(ss);
    float scale = rsqrtf(ss / (float)D_INNER + EPS);
    #pragma unroll
    for (int r = 0; r < 2; r++) {
        int c = threadIdx.x + r * 256;
        y[(size_t)tok * D_INNER + c] = v[r] * scale * nw[c];
    }
}

// ---------------- residual + RMSNorm ---------------------------------------
__global__ void __launch_bounds__(256)
resnorm_kernel(const float* __restrict__ o, float* __restrict__ act,
               const float* __restrict__ wgt)
{
    int tok = blockIdx.x, c = threadIdx.x;
    float v = o[(size_t)tok * HIDDEN + c] + act[(size_t)tok * HIDDEN + c];
    float ss = blockSum(v * v);
    act[(size_t)tok * HIDDEN + c] = v * rsqrtf(ss / (float)HIDDEN + EPS) * wgt[c];
}

// ---------------- LayerNorm ------------------------------------------------
__global__ void __launch_bounds__(256)
layernorm_kernel(const float* __restrict__ in, const float* __restrict__ w,
                 const float* __restrict__ bsl, float* __restrict__ out)
{
    int tok = blockIdx.x, c = threadIdx.x;
    float v = in[(size_t)tok * HIDDEN + c];
    float s  = blockSum(v);
    float s2 = blockSum(v * v);
    float m = s / (float)HIDDEN;
    float var = s2 / (float)HIDDEN - m * m;
    out[(size_t)tok * HIDDEN + c] = (v - m) * rsqrtf(var + EPS) * w[c] + bsl[c];
}

// ---------------- launch ----------------------------------------------------
extern "C" void kernel_launch(void* const* d_in, const int* in_sizes, int n_in,
                              void* d_out, int out_size)
{
    const float* x      = (const float*)d_in[0];
    const float* ip_w   = (const float*)d_in[1];
    const float* ip_b   = (const float*)d_in[2];
    const float* m_inw  = (const float*)d_in[3];
    const float* m_inb  = (const float*)d_in[4];
    const float* m_convw= (const float*)d_in[5];
    const float* m_convb= (const float*)d_in[6];
    const float* m_dtb  = (const float*)d_in[7];
    const float* m_Alog = (const float*)d_in[8];
    const float* m_D    = (const float*)d_in[9];
    const float* m_nw   = (const float*)d_in[10];
    const float* m_outw = (const float*)d_in[11];
    const float* m_outb = (const float*)d_in[12];
    const float* rms_w  = (const float*)d_in[13];
    const float* ln1_w  = (const float*)d_in[14];
    const float* ln1_b  = (const float*)d_in[15];
    const float* w1     = (const float*)d_in[16];
    const float* b1     = (const float*)d_in[17];
    const float* w2     = (const float*)d_in[18];
    const float* b2     = (const float*)d_in[19];
    const float* ln2_w  = (const float*)d_in[20];
    const float* ln2_b  = (const float*)d_in[21];
    float* out = (float*)d_out;

    float *act, *z, *xbc, *dt, *dA, *y, *o, *cum, *F, *Hin;
    cudaGetSymbolAddress((void**)&act, g_act);
    cudaGetSymbolAddress((void**)&z,   g_z);
    cudaGetSymbolAddress((void**)&xbc, g_xbc);
    cudaGetSymbolAddress((void**)&dt,  g_dt);
    cudaGetSymbolAddress((void**)&dA,  g_dA);
    cudaGetSymbolAddress((void**)&y,   g_y);
    cudaGetSymbolAddress((void**)&o,   g_o);
    cudaGetSymbolAddress((void**)&cum, g_cum);
    cudaGetSymbolAddress((void**)&F,   g_F);
    cudaGetSymbolAddress((void**)&Hin, g_Hin);

    const int SMB = SM_FLOATS * 4;   // 56832 bytes dynamic smem
    cudaFuncSetAttribute(tgemm_kernel<0>, cudaFuncAttributeMaxDynamicSharedMemorySize, SMB);
    cudaFuncSetAttribute(tgemm_kernel<1>, cudaFuncAttributeMaxDynamicSharedMemorySize, SMB);

    const int MB = NTOK / 128;   // 256 row-blocks

    tgemm_kernel<0><<<dim3((HIDDEN+127)/128, MB), 128, SMB>>>(
        x, ip_w, ip_b, act, NTOK, HIDDEN, INPUT_DIM);

    for (int i = 0; i < 2; i++) {
        tgemm_kernel<0><<<dim3((D_IN_PROJ + 127) / 128, MB), 128, SMB>>>(
            act, m_inw + (size_t)i * HIDDEN * D_IN_PROJ, m_inb + i * D_IN_PROJ,
            z, NTOK, D_IN_PROJ, HIDDEN);
        conv_kernel<<<dim3(5, NTOK / CTOK), 128>>>(
            z, m_convw + (size_t)i * CONV_DIM * KCONV,
            m_convb + i * CONV_DIM, m_dtb + i * NHEADS,
            m_Alog + i * NHEADS, xbc, dt, dA);
        scan_local_kernel<<<dim3(NHEADS, BATCH, NCH), 128>>>(
            xbc, dt, dA, m_D + i * NHEADS, y, cum, F);
        scan_combine_kernel<<<dim3(NHEADS, BATCH), 256>>>(F, cum, Hin);
        scan_fix_kernel<<<dim3(NHEADS, BATCH, NCH), 128>>>(xbc, cum, Hin, y);
        gatednorm_kernel<<<NTOK, 256>>>(y, z, m_nw + i * D_INNER);
        tgemm_kernel<0><<<dim3((HIDDEN+127)/128, MB), 128, SMB>>>(
            y, m_outw + (size_t)i * D_INNER * HIDDEN, m_outb + i * HIDDEN,
            o, NTOK, HIDDEN, D_INNER);
        resnorm_kernel<<<NTOK, 256>>>(o, act, rms_w + i * HIDDEN);
    }

    layernorm_kernel<<<NTOK, 256>>>(act, ln1_w, ln1_b, o);
    tgemm_kernel<1><<<dim3((2*HIDDEN + 127)/128, MB), 128, SMB>>>(
        o, w1, b1, y, NTOK, 2*HIDDEN, HIDDEN);
    tgemm_kernel<0><<<dim3((HIDDEN+127)/128, MB), 128, SMB>>>(
        y, w2, b2, o, NTOK, HIDDEN, 2*HIDDEN);
    layernorm_kernel<<<NTOK, 256>>>(o, ln2_w, ln2_b, out);
}

// round 13
// speedup vs baseline: 1.2902x; 1.0848x over previous
#include <cuda_runtime.h>
#include <cuda_bf16.h>
#include <math.h>

// ---------------- problem constants ----------------
#define BATCH      16
#define SEQ        2048
#define NTOK       (BATCH*SEQ)          // 32768
#define INPUT_DIM  1024
#define HIDDEN     256
#define D_STATE    32
#define D_INNER    512
#define NHEADS     16
#define HEADDIM    32
#define CONV_DIM   576
#define D_IN_PROJ  1104
#define KCONV      4
#define EPS        1e-5f
#define CHUNK      128
#define NCH        (SEQ/CHUNK)          // 16

// ---------------- scratch (device globals) ----------
__device__ __align__(128) float g_act [NTOK*HIDDEN];
__device__ __align__(128) float g_z   [NTOK*D_IN_PROJ];
__device__ __align__(128) float g_xbc [NTOK*CONV_DIM];
__device__ __align__(128) float g_dt  [NTOK*NHEADS];
__device__ __align__(128) float g_dA  [NTOK*NHEADS];
__device__ __align__(128) float g_y   [NTOK*D_INNER];
__device__ __align__(128) float g_o   [NTOK*HIDDEN];
__device__ __align__(128) float g_cum [NTOK*NHEADS];
__device__ __align__(128) float g_F   [BATCH*NHEADS*NCH*32*32];
__device__ __align__(128) float g_Hin [BATCH*NHEADS*NCH*32*32];

// ---------------- helpers ----------------
__device__ __forceinline__ float blockSum(float v) {
    __shared__ float sh[8];
    __shared__ float total;
    int lane = threadIdx.x & 31, wid = threadIdx.x >> 5;
    #pragma unroll
    for (int o = 16; o > 0; o >>= 1) v += __shfl_xor_sync(0xffffffffu, v, o);
    if (lane == 0) sh[wid] = v;
    __syncthreads();
    if (threadIdx.x == 0) {
        float t = 0.f;
        int nw = (int)(blockDim.x >> 5);
        for (int i = 0; i < nw; i++) t += sh[i];
        total = t;
    }
    __syncthreads();
    return total;
}

__device__ __forceinline__ float siluf(float x) { return x / (1.f + expf(-x)); }

__device__ __forceinline__ unsigned f2tf(float x) {
    unsigned r;
    asm("cvt.rna.tf32.f32 %0, %1;" : "=r"(r) : "f"(x));
    return r;
}

__device__ __forceinline__ void cp_async16(unsigned saddr, const void* gaddr) {
    asm volatile("cp.async.cg.shared.global [%0], [%1], 16;\n"
                 :: "r"(saddr), "l"(gaddr));
}
__device__ __forceinline__ void cp_async16_pred(unsigned saddr, const void* gaddr, int srcsz) {
    asm volatile("cp.async.cg.shared.global [%0], [%1], 16, %2;\n"
                 :: "r"(saddr), "l"(gaddr), "r"(srcsz));
}
__device__ __forceinline__ void cp_commit() { asm volatile("cp.async.commit_group;\n"); }
__device__ __forceinline__ void cp_wait1()  { asm volatile("cp.async.wait_group 1;\n"); }

// ---------------- TF32 tensor-core GEMM (FROZEN from round 9) ---------------
// Block 128x128x16, 128 threads = 4 warps (2x2), warp tile 64x64, 3-stage
// cp.async pipeline. tf32 conversion at fragment load (cvt.rna).
// MODE 0: C = A@W + bias.  MODE 1: gelu epilogue.
#define ASTR 20
#define BSTR 136
#define A_STG (128*ASTR)               // 2560 floats
#define B_STG (16*BSTR)                // 2176 floats
#define B_BASE (3*A_STG)               // 7680
#define SM_FLOATS (3*A_STG + 3*B_STG)  // 14208 floats = 56832 B

template<int MODE>
__global__ void __launch_bounds__(128)
tgemm_kernel(const float* __restrict__ A, const float* __restrict__ W,
             const float* __restrict__ bias, float* __restrict__ C,
             int M, int N, int K)
{
    extern __shared__ float sm[];
    int tid = threadIdx.x, lane = tid & 31, warp = tid >> 5;
    int wm = warp >> 1, wn = warp & 1;       // 2x2 warps, 64x64 each
    int gid = lane >> 2, tig = lane & 3;
    int row0 = blockIdx.y * 128, col0 = blockIdx.x * 128;

    int akq = tid & 3,  arb = tid >> 2;      // A: rows arb+p*32, float4 col akq
    int bnq = tid & 31, bkr = tid >> 5;      // B: rows bkr+p*4,  float4 col bnq

    const float* Abase = A + (size_t)row0 * K;
    int bcol = col0 + bnq * 4;
    int bsz  = (bcol < N) ? 16 : 0;

    float acc[4][8][4];
    #pragma unroll
    for (int i = 0; i < 4; i++)
        #pragma unroll
        for (int j = 0; j < 8; j++)
            #pragma unroll
            for (int q = 0; q < 4; q++) acc[i][j][q] = 0.f;

    unsigned smbase = (unsigned)__cvta_generic_to_shared(sm);
    int nkt = K >> 4;

    // prologue: stages 0,1
    #pragma unroll
    for (int s = 0; s < 2; s++) {
        if (s < nkt) {
            int kt = s << 4;
            #pragma unroll
            for (int p = 0; p < 4; p++)
                cp_async16(smbase + (s*A_STG + (arb + p*32)*ASTR + akq*4)*4,
                           &Abase[(size_t)(arb + p*32) * K + kt + akq*4]);
            #pragma unroll
            for (int p = 0; p < 4; p++)
                cp_async16_pred(smbase + (B_BASE + s*B_STG + (bkr + p*4)*BSTR + bnq*4)*4,
                                &W[(size_t)(kt + bkr + p*4) * N + bcol], bsz);
        }
        cp_commit();
    }

    for (int t = 0; t < nkt; t++) {
        cp_wait1();
        __syncthreads();

        // prefetch stage t+2
        {
            int tn = t + 2;
            if (tn < nkt) {
                int s = tn % 3;
                int kt = tn << 4;
                #pragma unroll
                for (int p = 0; p < 4; p++)
                    cp_async16(smbase + (s*A_STG + (arb + p*32)*ASTR + akq*4)*4,
                               &Abase[(size_t)(arb + p*32) * K + kt + akq*4]);
                #pragma unroll
                for (int p = 0; p < 4; p++)
                    cp_async16_pred(smbase + (B_BASE + s*B_STG + (bkr + p*4)*BSTR + bnq*4)*4,
                                    &W[(size_t)(kt + bkr + p*4) * N + bcol], bsz);
            }
            cp_commit();
        }

        const float* As = sm + (t % 3) * A_STG;
        const float* Bs = sm + B_BASE + (t % 3) * B_STG;

        #pragma unroll
        for (int kc = 0; kc < 2; kc++) {
            unsigned af[4][4], bf[8][2];
            #pragma unroll
            for (int im = 0; im < 4; im++) {
                const float* base = &As[(wm*64 + im*16 + gid)*ASTR + kc*8 + tig];
                af[im][0] = f2tf(base[0]);
                af[im][1] = f2tf(base[8*ASTR]);
                af[im][2] = f2tf(base[4]);
                af[im][3] = f2tf(base[8*ASTR + 4]);
            }
            #pragma unroll
            for (int jn = 0; jn < 8; jn++) {
                int cb = wn*64 + jn*8 + gid;
                bf[jn][0] = f2tf(Bs[(kc*8 + tig    )*BSTR + cb]);
                bf[jn][1] = f2tf(Bs[(kc*8 + tig + 4)*BSTR + cb]);
            }
            #pragma unroll
            for (int im = 0; im < 4; im++)
                #pragma unroll
                for (int jn = 0; jn < 8; jn++) {
                    asm volatile(
                        "mma.sync.aligned.m16n8k8.row.col.f32.tf32.tf32.f32 "
                        "{%0,%1,%2,%3}, {%4,%5,%6,%7}, {%8,%9}, {%0,%1,%2,%3};"
                        : "+f"(acc[im][jn][0]), "+f"(acc[im][jn][1]),
                          "+f"(acc[im][jn][2]), "+f"(acc[im][jn][3])
                        : "r"(af[im][0]), "r"(af[im][1]),
                          "r"(af[im][2]), "r"(af[im][3]),
                          "r"(bf[jn][0]), "r"(bf[jn][1]));
                }
        }
    }

    // epilogue
    #pragma unroll
    for (int im = 0; im < 4; im++) {
        #pragma unroll
        for (int jn = 0; jn < 8; jn++) {
            int col = col0 + wn*64 + jn*8 + tig*2;
            if (col >= N) continue;
            float b0 = bias[col], b1 = bias[col + 1];
            int r0 = row0 + wm*64 + im*16 + gid;
            float v0 = acc[im][jn][0] + b0;
            float v1 = acc[im][jn][1] + b1;
            float v2 = acc[im][jn][2] + b0;
            float v3 = acc[im][jn][3] + b1;
            if (MODE == 1) {
                v0 = 0.5f*v0*(1.f + erff(v0*0.70710678118654752f));
                v1 = 0.5f*v1*(1.f + erff(v1*0.70710678118654752f));
                v2 = 0.5f*v2*(1.f + erff(v2*0.70710678118654752f));
                v3 = 0.5f*v3*(1.f + erff(v3*0.70710678118654752f));
            }
            *reinterpret_cast<float2*>(&C[(size_t)r0 * N + col]) = make_float2(v0, v1);
            *reinterpret_cast<float2*>(&C[(size_t)(r0+8) * N + col]) = make_float2(v2, v3);
        }
    }
}

// ---------------- conv v2: channel-major, rolling window (KEPT, +70us win) --
#define CTOK 32
__global__ void __launch_bounds__(128)
conv_kernel(const float* __restrict__ z,
            const float* __restrict__ convw,
            const float* __restrict__ convb,
            const float* __restrict__ dtb,
            const float* __restrict__ Alog,
            float* __restrict__ xbc,
            float* __restrict__ dtO,
            float* __restrict__ dAO)
{
    int c = blockIdx.x * 128 + threadIdx.x;
    int tok0 = blockIdx.y * CTOK;
    int l0 = tok0 & (SEQ - 1);

    if (c < CONV_DIM) {
        float w0 = convw[c*KCONV + 0];
        float w1 = convw[c*KCONV + 1];
        float w2 = convw[c*KCONV + 2];
        float w3 = convw[c*KCONV + 3];
        float bv = convb[c];
        const float* zp = z + (size_t)tok0 * D_IN_PROJ + D_INNER + c;
        float xm3 = (l0 > 0) ? zp[-3 * D_IN_PROJ] : 0.f;
        float xm2 = (l0 > 0) ? zp[-2 * D_IN_PROJ] : 0.f;
        float xm1 = (l0 > 0) ? zp[-1 * D_IN_PROJ] : 0.f;
        float* xp = xbc + (size_t)tok0 * CONV_DIM + c;
        #pragma unroll 4
        for (int t = 0; t < CTOK; t++) {
            float x0 = zp[(size_t)t * D_IN_PROJ];
            float acc = bv;
            acc = fmaf(w0, xm3, acc);
            acc = fmaf(w1, xm2, acc);
            acc = fmaf(w2, xm1, acc);
            acc = fmaf(w3, x0,  acc);
            xp[(size_t)t * CONV_DIM] = siluf(acc);
            xm3 = xm2; xm2 = xm1; xm1 = x0;
        }
    } else if (c < CONV_DIM + NHEADS) {
        int hh = c - CONV_DIM;
        float db = dtb[hh];
        float nA = -expf(Alog[hh]);
        const float* zp = z + (size_t)tok0 * D_IN_PROJ + 2*D_INNER + 2*D_STATE + hh;
        #pragma unroll 4
        for (int t = 0; t < CTOK; t++) {
            float v = zp[(size_t)t * D_IN_PROJ] + db;
            float sp = (v > 20.f) ? v : log1pf(expf(v));
            int tok = tok0 + t;
            dtO[tok*NHEADS + hh] = sp;
            dAO[tok*NHEADS + hh] = expf(nA * sp);
        }
    }
}

// ---------------- chunked selective scan: pass 1 (R9 body, sdt scalar) -----
#define TT 32
__global__ void __launch_bounds__(128)
scan_local_kernel(const float* __restrict__ xbc, const float* __restrict__ dt,
                  const float* __restrict__ dA, const float* __restrict__ Dv,
                  float* __restrict__ y, float* __restrict__ cumO,
                  float* __restrict__ F)
{
    int hI = blockIdx.x;
    int b  = blockIdx.y;
    int ch = blockIdx.z;
    int lane = threadIdx.x & 31;
    int w    = threadIdx.x >> 5;
    float Dh = Dv[hI];

    float hs[8];
    #pragma unroll
    for (int i = 0; i < 8; i++) hs[i] = 0.f;
    float cum = 1.f;

    __shared__ float sB[TT][32];
    __shared__ float sC[TT][32];
    __shared__ float sxh[TT][32];
    __shared__ float sdt[TT];
    __shared__ float sdA[TT];
    __shared__ float scum[TT];
    __shared__ float ypart[4][TT][32];

    int tchunk0 = b * SEQ + ch * CHUNK;

    for (int tile = 0; tile < CHUNK / TT; tile++) {
        int t0 = tchunk0 + tile * TT;
        for (int j = threadIdx.x; j < TT * 32; j += 128) {
            int tl = j >> 5, c = j & 31;
            int tok = t0 + tl;
            const float* row = xbc + (size_t)tok * CONV_DIM;
            sB[tl][c] = row[D_INNER + c];
            sC[tl][c] = row[D_INNER + D_STATE + c];
            sxh[tl][c] = row[hI * HEADDIM + c];
        }
        if (threadIdx.x < TT) {
            sdt[threadIdx.x] = dt[(t0 + threadIdx.x) * NHEADS + hI];
            sdA[threadIdx.x] = dA[(t0 + threadIdx.x) * NHEADS + hI];
        }
        __syncthreads();

        for (int tl = 0; tl < TT; tl++) {
            float a  = sdA[tl];
            cum *= a;
            float dx = sdt[tl] * sxh[tl][lane];
            float acc = 0.f;
            #pragma unroll
            for (int i = 0; i < 8; i++) {
                int n = w * 8 + i;
                hs[i] = fmaf(hs[i], a, dx * sB[tl][n]);
                acc   = fmaf(hs[i], sC[tl][n], acc);
            }
            ypart[w][tl][lane] = acc;
            if (threadIdx.x == 0) scum[tl] = cum;
        }
        __syncthreads();

        for (int j = threadIdx.x; j < TT * 32; j += 128) {
            int tl = j >> 5, p = j & 31;
            int tok = t0 + tl;
            float yv = ypart[0][tl][p] + ypart[1][tl][p] +
                       ypart[2][tl][p] + ypart[3][tl][p] + Dh * sxh[tl][p];
            y[(size_t)tok * D_INNER + hI * HEADDIM + p] = yv;
            if (p == 0) cumO[tok * NHEADS + hI] = scum[tl];
        }
        __syncthreads();
    }

    size_t fbase = (size_t)(((b * NHEADS + hI) * NCH + ch)) * 1024;
    #pragma unroll
    for (int i = 0; i < 8; i++) {
        int n = w * 8 + i;
        F[fbase + n * 32 + lane] = hs[i];
    }
}

// ---------------- pass 2: combine chunk states -----------------------------
__global__ void __launch_bounds__(256)
scan_combine_kernel(const float* __restrict__ F, const float* __restrict__ cum,
                    float* __restrict__ Hin)
{
    int hI = blockIdx.x, b = blockIdx.y;
    size_t base = (size_t)((b * NHEADS + hI) * NCH) * 1024;
    int off = threadIdx.x * 4;
    float4 hr = make_float4(0.f, 0.f, 0.f, 0.f);
    for (int c = 0; c < NCH; c++) {
        *reinterpret_cast<float4*>(&Hin[base + (size_t)c * 1024 + off]) = hr;
        float P = cum[(size_t)(b * SEQ + c * CHUNK + CHUNK - 1) * NHEADS + hI];
        float4 f = *reinterpret_cast<const float4*>(&F[base + (size_t)c * 1024 + off]);
        hr.x = fmaf(hr.x, P, f.x);
        hr.y = fmaf(hr.y, P, f.y);
        hr.z = fmaf(hr.z, P, f.z);
        hr.w = fmaf(hr.w, P, f.w);
    }
}

// ---------------- pass 3: apply chunk-initial-state correction -------------
__global__ void __launch_bounds__(128)
scan_fix_kernel(const float* __restrict__ xbc, const float* __restrict__ cum,
                const float* __restrict__ Hin, float* __restrict__ y)
{
    int hI = blockIdx.x, b = blockIdx.y, ch = blockIdx.z;
    if (ch == 0) return;
    int lane = threadIdx.x & 31, w = threadIdx.x >> 5;

    __shared__ float sh[32][32];
    size_t base = (size_t)(((b * NHEADS + hI) * NCH + ch)) * 1024;
    for (int j = threadIdx.x; j < 1024; j += 128)
        sh[j >> 5][j & 31] = Hin[base + j];
    __syncthreads();

    int t0 = b * SEQ + ch * CHUNK + w * 32;
    for (int tt = 0; tt < 32; tt++) {
        int tok = t0 + tt;
        float cv = xbc[(size_t)tok * CONV_DIM + D_INNER + D_STATE + lane];
        float pt = cum[tok * NHEADS + hI];
        float a0 = 0.f, a1 = 0.f;
        #pragma unroll
        for (int n = 0; n < 32; n += 2) {
            a0 = fmaf(__shfl_sync(0xffffffffu, cv, n),     sh[n][lane],     a0);
            a1 = fmaf(__shfl_sync(0xffffffffu, cv, n + 1), sh[n + 1][lane], a1);
        }
        y[(size_t)tok * D_INNER + hI * HEADDIM + lane] += pt * (a0 + a1);
    }
}

// ---------------- gated RMSNorm --------------------------------------------
__global__ void __launch_bounds__(256)
gatednorm_kernel(float* __restrict__ y, const float* __restrict__ zx,
                 const float* __restrict__ nw)
{
    int tok = blockIdx.x;
    float v[2]; float ss = 0.f;
    #pragma unroll
    for (int r = 0; r < 2; r++) {
        int c = threadIdx.x + r * 256;
        float zv = zx[(size_t)tok * D_IN_PROJ + c];
        float yv = y[(size_t)tok * D_INNER + c];
        v[r] = yv * siluf(zv);
        ss += v[r] * v[r];
    }
    ss = blockSum(ss);
    float scale = rsqrtf(ss / (float)D_INNER + EPS);
    #pragma unroll
    for (int r = 0; r < 2; r++) {
        int c = threadIdx.x + r * 256;
        y[(size_t)tok * D_INNER + c] = v[r] * scale * nw[c];
    }
}

// ---------------- residual + RMSNorm ---------------------------------------
__global__ void __launch_bounds__(256)
resnorm_kernel(const float* __restrict__ o, float* __restrict__ act,
               const float* __restrict__ wgt)
{
    int tok = blockIdx.x, c = threadIdx.x;
    float v = o[(size_t)tok * HIDDEN + c] + act[(size_t)tok * HIDDEN + c];
    float ss = blockSum(v * v);
    act[(size_t)tok * HIDDEN + c] = v * rsqrtf(ss / (float)HIDDEN + EPS) * wgt[c];
}

// ---------------- LayerNorm ------------------------------------------------
__global__ void __launch_bounds__(256)
layernorm_kernel(const float* __restrict__ in, const float* __restrict__ w,
                 const float* __restrict__ bsl, float* __restrict__ out)
{
    int tok = blockIdx.x, c = threadIdx.x;
    float v = in[(size_t)tok * HIDDEN + c];
    float s  = blockSum(v);
    float s2 = blockSum(v * v);
    float m = s / (float)HIDDEN;
    float var = s2 / (float)HIDDEN - m * m;
    out[(size_t)tok * HIDDEN + c] = (v - m) * rsqrtf(var + EPS) * w[c] + bsl[c];
}

// ---------------- launch ----------------------------------------------------
extern "C" void kernel_launch(void* const* d_in, const int* in_sizes, int n_in,
                              void* d_out, int out_size)
{
    const float* x      = (const float*)d_in[0];
    const float* ip_w   = (const float*)d_in[1];
    const float* ip_b   = (const float*)d_in[2];
    const float* m_inw  = (const float*)d_in[3];
    const float* m_inb  = (const float*)d_in[4];
    const float* m_convw= (const float*)d_in[5];
    const float* m_convb= (const float*)d_in[6];
    const float* m_dtb  = (const float*)d_in[7];
    const float* m_Alog = (const float*)d_in[8];
    const float* m_D    = (const float*)d_in[9];
    const float* m_nw   = (const float*)d_in[10];
    const float* m_outw = (const float*)d_in[11];
    const float* m_outb = (const float*)d_in[12];
    const float* rms_w  = (const float*)d_in[13];
    const float* ln1_w  = (const float*)d_in[14];
    const float* ln1_b  = (const float*)d_in[15];
    const float* w1     = (const float*)d_in[16];
    const float* b1     = (const float*)d_in[17];
    const float* w2     = (const float*)d_in[18];
    const float* b2     = (const float*)d_in[19];
    const float* ln2_w  = (const float*)d_in[20];
    const float* ln2_b  = (const float*)d_in[21];
    float* out = (float*)d_out;

    float *act, *z, *xbc, *dt, *dA, *y, *o, *cum, *F, *Hin;
    cudaGetSymbolAddress((void**)&act, g_act);
    cudaGetSymbolAddress((void**)&z,   g_z);
    cudaGetSymbolAddress((void**)&xbc, g_xbc);
    cudaGetSymbolAddress((void**)&dt,  g_dt);
    cudaGetSymbolAddress((void**)&dA,  g_dA);
    cudaGetSymbolAddress((void**)&y,   g_y);
    cudaGetSymbolAddress((void**)&o,   g_o);
    cudaGetSymbolAddress((void**)&cum, g_cum);
    cudaGetSymbolAddress((void**)&F,   g_F);
    cudaGetSymbolAddress((void**)&Hin, g_Hin);

    const int SMB = SM_FLOATS * 4;   // 56832 bytes dynamic smem
    cudaFuncSetAttribute(tgemm_kernel<0>, cudaFuncAttributeMaxDynamicSharedMemorySize, SMB);
    cudaFuncSetAttribute(tgemm_kernel<1>, cudaFuncAttributeMaxDynamicSharedMemorySize, SMB);

    const int MB = NTOK / 128;   // 256 row-blocks

    tgemm_kernel<0><<<dim3((HIDDEN+127)/128, MB), 128, SMB>>>(
        x, ip_w, ip_b, act, NTOK, HIDDEN, INPUT_DIM);

    for (int i = 0; i < 2; i++) {
        tgemm_kernel<0><<<dim3((D_IN_PROJ + 127) / 128, MB), 128, SMB>>>(
            act, m_inw + (size_t)i * HIDDEN * D_IN_PROJ, m_inb + i * D_IN_PROJ,
            z, NTOK, D_IN_PROJ, HIDDEN);
        conv_kernel<<<dim3(5, NTOK / CTOK), 128>>>(
            z, m_convw + (size_t)i * CONV_DIM * KCONV,
            m_convb + i * CONV_DIM, m_dtb + i * NHEADS,
            m_Alog + i * NHEADS, xbc, dt, dA);
        scan_local_kernel<<<dim3(NHEADS, BATCH, NCH), 128>>>(
            xbc, dt, dA, m_D + i * NHEADS, y, cum, F);
        scan_combine_kernel<<<dim3(NHEADS, BATCH), 256>>>(F, cum, Hin);
        scan_fix_kernel<<<dim3(NHEADS, BATCH, NCH), 128>>>(xbc, cum, Hin, y);
        gatednorm_kernel<<<NTOK, 256>>>(y, z, m_nw + i * D_INNER);
        tgemm_kernel<0><<<dim3((HIDDEN+127)/128, MB), 128, SMB>>>(
            y, m_outw + (size_t)i * D_INNER * HIDDEN, m_outb + i * HIDDEN,
            o, NTOK, HIDDEN, D_INNER);
        resnorm_kernel<<<NTOK, 256>>>(o, act, rms_w + i * HIDDEN);
    }

    layernorm_kernel<<<NTOK, 256>>>(act, ln1_w, ln1_b, o);
    tgemm_kernel<1><<<dim3((2*HIDDEN + 127)/128, MB), 128, SMB>>>(
        o, w1, b1, y, NTOK, 2*HIDDEN, HIDDEN);
    tgemm_kernel<0><<<dim3((HIDDEN+127)/128, MB), 128, SMB>>>(
        y, w2, b2, o, NTOK, HIDDEN, 2*HIDDEN);
    layernorm_kernel<<<NTOK, 256>>>(o, ln2_w, ln2_b, out);
}

// round 15
// speedup vs baseline: 1.3031x; 1.0100x over previous
#include <cuda_runtime.h>
#include <cuda_bf16.h>
#include <math.h>

// ---------------- problem constants ----------------
#define BATCH      16
#define SEQ        2048
#define NTOK       (BATCH*SEQ)          // 32768
#define INPUT_DIM  1024
#define HIDDEN     256
#define D_STATE    32
#define D_INNER    512
#define NHEADS     16
#define HEADDIM    32
#define CONV_DIM   576
#define D_IN_PROJ  1104
#define KCONV      4
#define EPS        1e-5f
#define CHUNK      128
#define NCH        (SEQ/CHUNK)          // 16

// ---------------- scratch (device globals) ----------
__device__ __align__(128) float g_act [NTOK*HIDDEN];
__device__ __align__(128) float g_z   [NTOK*D_IN_PROJ];
__device__ __align__(128) float g_xbc [NTOK*CONV_DIM];
__device__ __align__(128) float g_dt  [NTOK*NHEADS];
__device__ __align__(128) float g_dA  [NTOK*NHEADS];
__device__ __align__(128) float g_y   [NTOK*D_INNER];
__device__ __align__(128) float g_o   [NTOK*HIDDEN];
__device__ __align__(128) float g_cum [NTOK*NHEADS];
__device__ __align__(128) float g_F   [BATCH*NHEADS*NCH*32*32];
__device__ __align__(128) float g_Hin [BATCH*NHEADS*NCH*32*32];

// ---------------- helpers ----------------
__device__ __forceinline__ float blockSum(float v) {
    __shared__ float sh[8];
    __shared__ float total;
    int lane = threadIdx.x & 31, wid = threadIdx.x >> 5;
    #pragma unroll
    for (int o = 16; o > 0; o >>= 1) v += __shfl_xor_sync(0xffffffffu, v, o);
    if (lane == 0) sh[wid] = v;
    __syncthreads();
    if (threadIdx.x == 0) {
        float t = 0.f;
        int nw = (int)(blockDim.x >> 5);
        for (int i = 0; i < nw; i++) t += sh[i];
        total = t;
    }
    __syncthreads();
    return total;
}

__device__ __forceinline__ float siluf(float x) { return x / (1.f + expf(-x)); }

__device__ __forceinline__ unsigned f2tf(float x) {
    unsigned r;
    asm("cvt.rna.tf32.f32 %0, %1;" : "=r"(r) : "f"(x));
    return r;
}

__device__ __forceinline__ void cp_async16(unsigned saddr, const void* gaddr) {
    asm volatile("cp.async.cg.shared.global [%0], [%1], 16;\n"
                 :: "r"(saddr), "l"(gaddr));
}
__device__ __forceinline__ void cp_async16_pred(unsigned saddr, const void* gaddr, int srcsz) {
    asm volatile("cp.async.cg.shared.global [%0], [%1], 16, %2;\n"
                 :: "r"(saddr), "l"(gaddr), "r"(srcsz));
}
__device__ __forceinline__ void cp_commit() { asm volatile("cp.async.commit_group;\n"); }
__device__ __forceinline__ void cp_wait1()  { asm volatile("cp.async.wait_group 1;\n"); }

// ---------------- TF32 tensor-core GEMM (FROZEN from round 9) ---------------
#define ASTR 20
#define BSTR 136
#define A_STG (128*ASTR)               // 2560 floats
#define B_STG (16*BSTR)                // 2176 floats
#define B_BASE (3*A_STG)               // 7680
#define SM_FLOATS (3*A_STG + 3*B_STG)  // 14208 floats = 56832 B

template<int MODE>
__global__ void __launch_bounds__(128)
tgemm_kernel(const float* __restrict__ A, const float* __restrict__ W,
             const float* __restrict__ bias, float* __restrict__ C,
             int M, int N, int K)
{
    extern __shared__ float sm[];
    int tid = threadIdx.x, lane = tid & 31, warp = tid >> 5;
    int wm = warp >> 1, wn = warp & 1;       // 2x2 warps, 64x64 each
    int gid = lane >> 2, tig = lane & 3;
    int row0 = blockIdx.y * 128, col0 = blockIdx.x * 128;

    int akq = tid & 3,  arb = tid >> 2;
    int bnq = tid & 31, bkr = tid >> 5;

    const float* Abase = A + (size_t)row0 * K;
    int bcol = col0 + bnq * 4;
    int bsz  = (bcol < N) ? 16 : 0;

    float acc[4][8][4];
    #pragma unroll
    for (int i = 0; i < 4; i++)
        #pragma unroll
        for (int j = 0; j < 8; j++)
            #pragma unroll
            for (int q = 0; q < 4; q++) acc[i][j][q] = 0.f;

    unsigned smbase = (unsigned)__cvta_generic_to_shared(sm);
    int nkt = K >> 4;

    #pragma unroll
    for (int s = 0; s < 2; s++) {
        if (s < nkt) {
            int kt = s << 4;
            #pragma unroll
            for (int p = 0; p < 4; p++)
                cp_async16(smbase + (s*A_STG + (arb + p*32)*ASTR + akq*4)*4,
                           &Abase[(size_t)(arb + p*32) * K + kt + akq*4]);
            #pragma unroll
            for (int p = 0; p < 4; p++)
                cp_async16_pred(smbase + (B_BASE + s*B_STG + (bkr + p*4)*BSTR + bnq*4)*4,
                                &W[(size_t)(kt + bkr + p*4) * N + bcol], bsz);
        }
        cp_commit();
    }

    for (int t = 0; t < nkt; t++) {
        cp_wait1();
        __syncthreads();

        {
            int tn = t + 2;
            if (tn < nkt) {
                int s = tn % 3;
                int kt = tn << 4;
                #pragma unroll
                for (int p = 0; p < 4; p++)
                    cp_async16(smbase + (s*A_STG + (arb + p*32)*ASTR + akq*4)*4,
                               &Abase[(size_t)(arb + p*32) * K + kt + akq*4]);
                #pragma unroll
                for (int p = 0; p < 4; p++)
                    cp_async16_pred(smbase + (B_BASE + s*B_STG + (bkr + p*4)*BSTR + bnq*4)*4,
                                    &W[(size_t)(kt + bkr + p*4) * N + bcol], bsz);
            }
            cp_commit();
        }

        const float* As = sm + (t % 3) * A_STG;
        const float* Bs = sm + B_BASE + (t % 3) * B_STG;

        #pragma unroll
        for (int kc = 0; kc < 2; kc++) {
            unsigned af[4][4], bf[8][2];
            #pragma unroll
            for (int im = 0; im < 4; im++) {
                const float* base = &As[(wm*64 + im*16 + gid)*ASTR + kc*8 + tig];
                af[im][0] = f2tf(base[0]);
                af[im][1] = f2tf(base[8*ASTR]);
                af[im][2] = f2tf(base[4]);
                af[im][3] = f2tf(base[8*ASTR + 4]);
            }
            #pragma unroll
            for (int jn = 0; jn < 8; jn++) {
                int cb = wn*64 + jn*8 + gid;
                bf[jn][0] = f2tf(Bs[(kc*8 + tig    )*BSTR + cb]);
                bf[jn][1] = f2tf(Bs[(kc*8 + tig + 4)*BSTR + cb]);
            }
            #pragma unroll
            for (int im = 0; im < 4; im++)
                #pragma unroll
                for (int jn = 0; jn < 8; jn++) {
                    asm volatile(
                        "mma.sync.aligned.m16n8k8.row.col.f32.tf32.tf32.f32 "
                        "{%0,%1,%2,%3}, {%4,%5,%6,%7}, {%8,%9}, {%0,%1,%2,%3};"
                        : "+f"(acc[im][jn][0]), "+f"(acc[im][jn][1]),
                          "+f"(acc[im][jn][2]), "+f"(acc[im][jn][3])
                        : "r"(af[im][0]), "r"(af[im][1]),
                          "r"(af[im][2]), "r"(af[im][3]),
                          "r"(bf[jn][0]), "r"(bf[jn][1]));
                }
        }
    }

    #pragma unroll
    for (int im = 0; im < 4; im++) {
        #pragma unroll
        for (int jn = 0; jn < 8; jn++) {
            int col = col0 + wn*64 + jn*8 + tig*2;
            if (col >= N) continue;
            float b0 = bias[col], b1 = bias[col + 1];
            int r0 = row0 + wm*64 + im*16 + gid;
            float v0 = acc[im][jn][0] + b0;
            float v1 = acc[im][jn][1] + b1;
            float v2 = acc[im][jn][2] + b0;
            float v3 = acc[im][jn][3] + b1;
            if (MODE == 1) {
                v0 = 0.5f*v0*(1.f + erff(v0*0.70710678118654752f));
                v1 = 0.5f*v1*(1.f + erff(v1*0.70710678118654752f));
                v2 = 0.5f*v2*(1.f + erff(v2*0.70710678118654752f));
                v3 = 0.5f*v3*(1.f + erff(v3*0.70710678118654752f));
            }
            *reinterpret_cast<float2*>(&C[(size_t)r0 * N + col]) = make_float2(v0, v1);
            *reinterpret_cast<float2*>(&C[(size_t)(r0+8) * N + col]) = make_float2(v2, v3);
        }
    }
}

// ---------------- conv v2: channel-major, rolling window --------------------
#define CTOK 32
__global__ void __launch_bounds__(128)
conv_kernel(const float* __restrict__ z,
            const float* __restrict__ convw,
            const float* __restrict__ convb,
            const float* __restrict__ dtb,
            const float* __restrict__ Alog,
            float* __restrict__ xbc,
            float* __restrict__ dtO,
            float* __restrict__ dAO)
{
    int c = blockIdx.x * 128 + threadIdx.x;
    int tok0 = blockIdx.y * CTOK;
    int l0 = tok0 & (SEQ - 1);

    if (c < CONV_DIM) {
        float w0 = convw[c*KCONV + 0];
        float w1 = convw[c*KCONV + 1];
        float w2 = convw[c*KCONV + 2];
        float w3 = convw[c*KCONV + 3];
        float bv = convb[c];
        const float* zp = z + (size_t)tok0 * D_IN_PROJ + D_INNER + c;
        float xm3 = (l0 > 0) ? zp[-3 * D_IN_PROJ] : 0.f;
        float xm2 = (l0 > 0) ? zp[-2 * D_IN_PROJ] : 0.f;
        float xm1 = (l0 > 0) ? zp[-1 * D_IN_PROJ] : 0.f;
        float* xp = xbc + (size_t)tok0 * CONV_DIM + c;
        #pragma unroll 4
        for (int t = 0; t < CTOK; t++) {
            float x0 = zp[(size_t)t * D_IN_PROJ];
            float acc = bv;
            acc = fmaf(w0, xm3, acc);
            acc = fmaf(w1, xm2, acc);
            acc = fmaf(w2, xm1, acc);
            acc = fmaf(w3, x0,  acc);
            xp[(size_t)t * CONV_DIM] = siluf(acc);
            xm3 = xm2; xm2 = xm1; xm1 = x0;
        }
    } else if (c < CONV_DIM + NHEADS) {
        int hh = c - CONV_DIM;
        float db = dtb[hh];
        float nA = -expf(Alog[hh]);
        const float* zp = z + (size_t)tok0 * D_IN_PROJ + 2*D_INNER + 2*D_STATE + hh;
        #pragma unroll 4
        for (int t = 0; t < CTOK; t++) {
            float v = zp[(size_t)t * D_IN_PROJ] + db;
            float sp = (v > 20.f) ? v : log1pf(expf(v));
            int tok = tok0 + t;
            dtO[tok*NHEADS + hh] = sp;
            dAO[tok*NHEADS + hh] = expf(nA * sp);
        }
    }
}

// ---------------- chunked selective scan: pass 1 (float4 B/C loads) --------
#define TT 32
__global__ void __launch_bounds__(128)
scan_local_kernel(const float* __restrict__ xbc, const float* __restrict__ dt,
                  const float* __restrict__ dA, const float* __restrict__ Dv,
                  float* __restrict__ y, float* __restrict__ cumO,
                  float* __restrict__ F)
{
    int hI = blockIdx.x;
    int b  = blockIdx.y;
    int ch = blockIdx.z;
    int lane = threadIdx.x & 31;
    int w    = threadIdx.x >> 5;
    float Dh = Dv[hI];

    float hs[8];
    #pragma unroll
    for (int i = 0; i < 8; i++) hs[i] = 0.f;
    float cum = 1.f;

    __shared__ float sB[TT][32];
    __shared__ float sC[TT][32];
    __shared__ float sxh[TT][32];
    __shared__ float sdt[TT];
    __shared__ float sdA[TT];
    __shared__ float scum[TT];
    __shared__ float ypart[4][TT][32];

    int tchunk0 = b * SEQ + ch * CHUNK;

    for (int tile = 0; tile < CHUNK / TT; tile++) {
        int t0 = tchunk0 + tile * TT;
        for (int j = threadIdx.x; j < TT * 32; j += 128) {
            int tl = j >> 5, c = j & 31;
            int tok = t0 + tl;
            const float* row = xbc + (size_t)tok * CONV_DIM;
            sB[tl][c] = row[D_INNER + c];
            sC[tl][c] = row[D_INNER + D_STATE + c];
            sxh[tl][c] = row[hI * HEADDIM + c];
        }
        if (threadIdx.x < TT) {
            sdt[threadIdx.x] = dt[(t0 + threadIdx.x) * NHEADS + hI];
            sdA[threadIdx.x] = dA[(t0 + threadIdx.x) * NHEADS + hI];
        }
        __syncthreads();

        for (int tl = 0; tl < TT; tl++) {
            float a  = sdA[tl];
            cum *= a;
            float dx = sdt[tl] * sxh[tl][lane];
            // vectorized broadcast loads of this warp's 8 B/C values
            float4 b0 = *reinterpret_cast<const float4*>(&sB[tl][w * 8]);
            float4 b1 = *reinterpret_cast<const float4*>(&sB[tl][w * 8 + 4]);
            float4 c0 = *reinterpret_cast<const float4*>(&sC[tl][w * 8]);
            float4 c1 = *reinterpret_cast<const float4*>(&sC[tl][w * 8 + 4]);
            float bb[8] = {b0.x, b0.y, b0.z, b0.w, b1.x, b1.y, b1.z, b1.w};
            float cc[8] = {c0.x, c0.y, c0.z, c0.w, c1.x, c1.y, c1.z, c1.w};
            float acc = 0.f;
            #pragma unroll
            for (int i = 0; i < 8; i++) {
                hs[i] = fmaf(hs[i], a, dx * bb[i]);
                acc   = fmaf(hs[i], cc[i], acc);
            }
            ypart[w][tl][lane] = acc;
            if (threadIdx.x == 0) scum[tl] = cum;
        }
        __syncthreads();

        for (int j = threadIdx.x; j < TT * 32; j += 128) {
            int tl = j >> 5, p = j & 31;
            int tok = t0 + tl;
            float yv = ypart[0][tl][p] + ypart[1][tl][p] +
                       ypart[2][tl][p] + ypart[3][tl][p] + Dh * sxh[tl][p];
            y[(size_t)tok * D_INNER + hI * HEADDIM + p] = yv;
            if (p == 0) cumO[tok * NHEADS + hI] = scum[tl];
        }
        __syncthreads();
    }

    size_t fbase = (size_t)(((b * NHEADS + hI) * NCH + ch)) * 1024;
    #pragma unroll
    for (int i = 0; i < 8; i++) {
        int n = w * 8 + i;
        F[fbase + n * 32 + lane] = hs[i];
    }
}

// ---------------- pass 2: combine chunk states -----------------------------
__global__ void __launch_bounds__(256)
scan_combine_kernel(const float* __restrict__ F, const float* __restrict__ cum,
                    float* __restrict__ Hin)
{
    int hI = blockIdx.x, b = blockIdx.y;
    size_t base = (size_t)((b * NHEADS + hI) * NCH) * 1024;
    int off = threadIdx.x * 4;
    float4 hr = make_float4(0.f, 0.f, 0.f, 0.f);
    for (int c = 0; c < NCH; c++) {
        *reinterpret_cast<float4*>(&Hin[base + (size_t)c * 1024 + off]) = hr;
        float P = cum[(size_t)(b * SEQ + c * CHUNK + CHUNK - 1) * NHEADS + hI];
        float4 f = *reinterpret_cast<const float4*>(&F[base + (size_t)c * 1024 + off]);
        hr.x = fmaf(hr.x, P, f.x);
        hr.y = fmaf(hr.y, P, f.y);
        hr.z = fmaf(hr.z, P, f.z);
        hr.w = fmaf(hr.w, P, f.w);
    }
}

// ---------------- pass 3: apply chunk-initial-state correction -------------
__global__ void __launch_bounds__(128)
scan_fix_kernel(const float* __restrict__ xbc, const float* __restrict__ cum,
                const float* __restrict__ Hin, float* __restrict__ y)
{
    int hI = blockIdx.x, b = blockIdx.y, ch = blockIdx.z;
    if (ch == 0) return;
    int lane = threadIdx.x & 31, w = threadIdx.x >> 5;

    __shared__ float sh[32][32];
    size_t base = (size_t)(((b * NHEADS + hI) * NCH + ch)) * 1024;
    for (int j = threadIdx.x; j < 1024; j += 128)
        sh[j >> 5][j & 31] = Hin[base + j];
    __syncthreads();

    int t0 = b * SEQ + ch * CHUNK + w * 32;
    for (int tt = 0; tt < 32; tt++) {
        int tok = t0 + tt;
        float cv = xbc[(size_t)tok * CONV_DIM + D_INNER + D_STATE + lane];
        float pt = cum[tok * NHEADS + hI];
        float a0 = 0.f, a1 = 0.f;
        #pragma unroll
        for (int n = 0; n < 32; n += 2) {
            a0 = fmaf(__shfl_sync(0xffffffffu, cv, n),     sh[n][lane],     a0);
            a1 = fmaf(__shfl_sync(0xffffffffu, cv, n + 1), sh[n + 1][lane], a1);
        }
        y[(size_t)tok * D_INNER + hI * HEADDIM + lane] += pt * (a0 + a1);
    }
}

// ---------------- gated RMSNorm --------------------------------------------
__global__ void __launch_bounds__(256)
gatednorm_kernel(float* __restrict__ y, const float* __restrict__ zx,
                 const float* __restrict__ nw)
{
    int tok = blockIdx.x;
    float v[2]; float ss = 0.f;
    #pragma unroll
    for (int r = 0; r < 2; r++) {
        int c = threadIdx.x + r * 256;
        float zv = zx[(size_t)tok * D_IN_PROJ + c];
        float yv = y[(size_t)tok * D_INNER + c];
        v[r] = yv * siluf(zv);
        ss += v[r] * v[r];
    }
    ss = blockSum(ss);
    float scale = rsqrtf(ss / (float)D_INNER + EPS);
    #pragma unroll
    for (int r = 0; r < 2; r++) {
        int c = threadIdx.x + r * 256;
        y[(size_t)tok * D_INNER + c] = v[r] * scale * nw[c];
    }
}

// ---------------- residual + RMSNorm (+ optional fused LayerNorm) -----------
// DOLN=0: act = rmsnorm(o+act, wgt).
// DOLN=1: additionally lnout = layernorm(act_new, lnw, lnb) -- identical ops
//         to the standalone layernorm kernel applied to act_new.
template<int DOLN>
__global__ void __launch_bounds__(256)
resnorm_kernel(const float* __restrict__ o, float* __restrict__ act,
               const float* __restrict__ wgt,
               const float* __restrict__ lnw, const float* __restrict__ lnb,
               float* __restrict__ lnout)
{
    int tok = blockIdx.x, c = threadIdx.x;
    float v = o[(size_t)tok * HIDDEN + c] + act[(size_t)tok * HIDDEN + c];
    float ss = blockSum(v * v);
    float r = v * rsqrtf(ss / (float)HIDDEN + EPS) * wgt[c];
    act[(size_t)tok * HIDDEN + c] = r;
    if (DOLN) {
        float s  = blockSum(r);
        float s2 = blockSum(r * r);
        float m = s / (float)HIDDEN;
        float var = s2 / (float)HIDDEN - m * m;
        lnout[(size_t)tok * HIDDEN + c] = (r - m) * rsqrtf(var + EPS) * lnw[c] + lnb[c];
    }
}

// ---------------- LayerNorm ------------------------------------------------
__global__ void __launch_bounds__(256)
layernorm_kernel(const float* __restrict__ in, const float* __restrict__ w,
                 const float* __restrict__ bsl, float* __restrict__ out)
{
    int tok = blockIdx.x, c = threadIdx.x;
    float v = in[(size_t)tok * HIDDEN + c];
    float s  = blockSum(v);
    float s2 = blockSum(v * v);
    float m = s / (float)HIDDEN;
    float var = s2 / (float)HIDDEN - m * m;
    out[(size_t)tok * HIDDEN + c] = (v - m) * rsqrtf(var + EPS) * w[c] + bsl[c];
}

// ---------------- launch ----------------------------------------------------
extern "C" void kernel_launch(void* const* d_in, const int* in_sizes, int n_in,
                              void* d_out, int out_size)
{
    const float* x      = (const float*)d_in[0];
    const float* ip_w   = (const float*)d_in[1];
    const float* ip_b   = (const float*)d_in[2];
    const float* m_inw  = (const float*)d_in[3];
    const float* m_inb  = (const float*)d_in[4];
    const float* m_convw= (const float*)d_in[5];
    const float* m_convb= (const float*)d_in[6];
    const float* m_dtb  = (const float*)d_in[7];
    const float* m_Alog = (const float*)d_in[8];
    const float* m_D    = (const float*)d_in[9];
    const float* m_nw   = (const float*)d_in[10];
    const float* m_outw = (const float*)d_in[11];
    const float* m_outb = (const float*)d_in[12];
    const float* rms_w  = (const float*)d_in[13];
    const float* ln1_w  = (const float*)d_in[14];
    const float* ln1_b  = (const float*)d_in[15];
    const float* w1     = (const float*)d_in[16];
    const float* b1     = (const float*)d_in[17];
    const float* w2     = (const float*)d_in[18];
    const float* b2     = (const float*)d_in[19];
    const float* ln2_w  = (const float*)d_in[20];
    const float* ln2_b  = (const float*)d_in[21];
    float* out = (float*)d_out;

    float *act, *z, *xbc, *dt, *dA, *y, *o, *cum, *F, *Hin;
    cudaGetSymbolAddress((void**)&act, g_act);
    cudaGetSymbolAddress((void**)&z,   g_z);
    cudaGetSymbolAddress((void**)&xbc, g_xbc);
    cudaGetSymbolAddress((void**)&dt,  g_dt);
    cudaGetSymbolAddress((void**)&dA,  g_dA);
    cudaGetSymbolAddress((void**)&y,   g_y);
    cudaGetSymbolAddress((void**)&o,   g_o);
    cudaGetSymbolAddress((void**)&cum, g_cum);
    cudaGetSymbolAddress((void**)&F,   g_F);
    cudaGetSymbolAddress((void**)&Hin, g_Hin);

    const int SMB = SM_FLOATS * 4;   // 56832 bytes dynamic smem
    cudaFuncSetAttribute(tgemm_kernel<0>, cudaFuncAttributeMaxDynamicSharedMemorySize, SMB);
    cudaFuncSetAttribute(tgemm_kernel<1>, cudaFuncAttributeMaxDynamicSharedMemorySize, SMB);

    const int MB = NTOK / 128;   // 256 row-blocks

    tgemm_kernel<0><<<dim3((HIDDEN+127)/128, MB), 128, SMB>>>(
        x, ip_w, ip_b, act, NTOK, HIDDEN, INPUT_DIM);

    for (int i = 0; i < 2; i++) {
        tgemm_kernel<0><<<dim3((D_IN_PROJ + 127) / 128, MB), 128, SMB>>>(
            act, m_inw + (size_t)i * HIDDEN * D_IN_PROJ, m_inb + i * D_IN_PROJ,
            z, NTOK, D_IN_PROJ, HIDDEN);
        conv_kernel<<<dim3(5, NTOK / CTOK), 128>>>(
            z, m_convw + (size_t)i * CONV_DIM * KCONV,
            m_convb + i * CONV_DIM, m_dtb + i * NHEADS,
            m_Alog + i * NHEADS, xbc, dt, dA);
        scan_local_kernel<<<dim3(NHEADS, BATCH, NCH), 128>>>(
            xbc, dt, dA, m_D + i * NHEADS, y, cum, F);
        scan_combine_kernel<<<dim3(NHEADS, BATCH), 256>>>(F, cum, Hin);
        scan_fix_kernel<<<dim3(NHEADS, BATCH, NCH), 128>>>(xbc, cum, Hin, y);
        gatednorm_kernel<<<NTOK, 256>>>(y, z, m_nw + i * D_INNER);
        tgemm_kernel<0><<<dim3((HIDDEN+127)/128, MB), 128, SMB>>>(
            y, m_outw + (size_t)i * D_INNER * HIDDEN, m_outb + i * HIDDEN,
            o, NTOK, HIDDEN, D_INNER);
        if (i == 0)
            resnorm_kernel<0><<<NTOK, 256>>>(o, act, rms_w + i * HIDDEN,
                                             (const float*)nullptr, (const float*)nullptr,
                                             (float*)nullptr);
        else
            resnorm_kernel<1><<<NTOK, 256>>>(o, act, rms_w + i * HIDDEN,
                                             ln1_w, ln1_b, o);   // fused ln1 -> o
    }

    // MLP head (ln1 already applied into o by fused resnorm)
    tgemm_kernel<1><<<dim3((2*HIDDEN + 127)/128, MB), 128, SMB>>>(
        o, w1, b1, y, NTOK, 2*HIDDEN, HIDDEN);
    tgemm_kernel<0><<<dim3((HIDDEN+127)/128, MB), 128, SMB>>>(
        y, w2, b2, o, NTOK, HIDDEN, 2*HIDDEN);
    layernorm_kernel<<<NTOK, 256>>>(o, ln2_w, ln2_b, out);
}

// round 17
// speedup vs baseline: 1.5007x; 1.1517x over previous
#include <cuda_runtime.h>
#include <cuda_fp16.h>
#include <math.h>

// ---------------- problem constants ----------------
#define BATCH      16
#define SEQ        2048
#define NTOK       (BATCH*SEQ)          // 32768
#define INPUT_DIM  1024
#define HIDDEN     256
#define D_STATE    32
#define D_INNER    512
#define NHEADS     16
#define HEADDIM    32
#define CONV_DIM   576
#define D_IN_PROJ  1104
#define KCONV      4
#define EPS        1e-5f
#define CHUNK      128
#define NCH        (SEQ/CHUNK)          // 16

// ---------------- scratch (device globals) ----------
__device__ __align__(128) float g_act [NTOK*HIDDEN];
__device__ __align__(128) float g_z   [NTOK*D_IN_PROJ];
__device__ __align__(128) float g_xbc [NTOK*CONV_DIM];
__device__ __align__(128) float g_dt  [NTOK*NHEADS];
__device__ __align__(128) float g_dA  [NTOK*NHEADS];
__device__ __align__(128) float g_y   [NTOK*D_INNER];
__device__ __align__(128) float g_o   [NTOK*HIDDEN];
__device__ __align__(128) float g_cum [NTOK*NHEADS];
__device__ __align__(128) float g_F   [BATCH*NHEADS*NCH*32*32];
__device__ __align__(128) float g_Hin [BATCH*NHEADS*NCH*32*32];

// fp16 operand buffers
__device__ __align__(128) __half g_xh  [NTOK*INPUT_DIM];
__device__ __align__(128) __half g_acth[NTOK*HIDDEN];
__device__ __align__(128) __half g_yh  [NTOK*D_INNER];
__device__ __align__(128) __half g_lh  [NTOK*HIDDEN];
__device__ __align__(128) __half g_wh  [1351680];

// offsets into g_wh (transposed [N][K] layout)
#define OFF_IPW  0
#define OFF_INW  262144
#define OFF_OUTW 827392
#define OFF_W1   1089536
#define OFF_W2   1220608

// ---------------- helpers ----------------
__device__ __forceinline__ float blockSum(float v) {
    __shared__ float sh[8];
    __shared__ float total;
    int lane = threadIdx.x & 31, wid = threadIdx.x >> 5;
    #pragma unroll
    for (int o = 16; o > 0; o >>= 1) v += __shfl_xor_sync(0xffffffffu, v, o);
    if (lane == 0) sh[wid] = v;
    __syncthreads();
    if (threadIdx.x == 0) {
        float t = 0.f;
        int nw = (int)(blockDim.x >> 5);
        for (int i = 0; i < nw; i++) t += sh[i];
        total = t;
    }
    __syncthreads();
    return total;
}

__device__ __forceinline__ float siluf(float x) { return x / (1.f + expf(-x)); }

__device__ __forceinline__ void cp_async16(unsigned saddr, const void* gaddr) {
    asm volatile("cp.async.cg.shared.global [%0], [%1], 16;\n"
                 :: "r"(saddr), "l"(gaddr));
}
__device__ __forceinline__ void cp_async16_pred(unsigned saddr, const void* gaddr, int srcsz) {
    asm volatile("cp.async.cg.shared.global [%0], [%1], 16, %2;\n"
                 :: "r"(saddr), "l"(gaddr), "r"(srcsz));
}
__device__ __forceinline__ void cp_commit() { asm volatile("cp.async.commit_group;\n"); }
__device__ __forceinline__ void cp_wait1()  { asm volatile("cp.async.wait_group 1;\n"); }

// ---------------- fp16 tensor-core GEMM -------------------------------------
// C[M,N] = A[M,K] @ W[N,K]^T + bias via mma.m16n8k16.f16 (single product).
// Block 128x128x16, 128 threads = 4 warps (2x2), warp tile 64x64, 3-stage
// cp.async. Smem per plane: [128 rows][12 u32] (fragment layout proven in R10).
// MODE 0: C fp32.  MODE 1: gelu -> Ch fp16.  MODE 2: C fp32 + Ch fp16.
#define PL_U32  (128*12)          // 1536 u32 per plane
#define STG_U32 (2*PL_U32)        // A + B per stage
#define SMB_GEMM (3*STG_U32*4)    // 36864 bytes

template<int MODE>
__global__ void __launch_bounds__(128)
hgemm_kernel(const __half* __restrict__ A, const __half* __restrict__ W,
             const float* __restrict__ bias, float* __restrict__ C,
             __half* __restrict__ Ch,
             int M, int N, int K)
{
    extern __shared__ unsigned smu[];
    int tid = threadIdx.x, lane = tid & 31, warp = tid >> 5;
    int wm = warp >> 1, wn = warp & 1;        // 2x2 warps, 64x64 each
    int gid = lane >> 2, tig = lane & 3;
    int row0 = blockIdx.y * 128, col0 = blockIdx.x * 128;

    int ac = tid & 1;       // 16B chunk within 32B row-slab
    int ar = tid >> 1;      // rows ar, ar+64

    unsigned smbase = (unsigned)__cvta_generic_to_shared(smu);

    float acc[4][8][4];
    #pragma unroll
    for (int i = 0; i < 4; i++)
        #pragma unroll
        for (int j = 0; j < 8; j++)
            #pragma unroll
            for (int q = 0; q < 4; q++) acc[i][j][q] = 0.f;

    int nB0 = col0 + ar, nB1 = col0 + ar + 64;
    int szB0 = (nB0 < N) ? 16 : 0, szB1 = (nB1 < N) ? 16 : 0;

    int nkt = K >> 4;

    auto load_tile = [&](int s, int kt) {
        unsigned sb = smbase + (unsigned)(s * STG_U32) * 4;
        // A plane
        cp_async16(sb + (unsigned)(ar * 12 + ac * 4) * 4,
                   A + (size_t)(row0 + ar) * K + kt + ac * 8);
        cp_async16(sb + (unsigned)((ar + 64) * 12 + ac * 4) * 4,
                   A + (size_t)(row0 + ar + 64) * K + kt + ac * 8);
        // B plane
        unsigned pb = sb + (unsigned)PL_U32 * 4;
        cp_async16_pred(pb + (unsigned)(ar * 12 + ac * 4) * 4,
                        W + (size_t)nB0 * K + kt + ac * 8, szB0);
        cp_async16_pred(pb + (unsigned)((ar + 64) * 12 + ac * 4) * 4,
                        W + (size_t)nB1 * K + kt + ac * 8, szB1);
        cp_commit();
    };

    load_tile(0, 0);
    if (nkt > 1) load_tile(1, 16); else cp_commit();

    for (int t = 0; t < nkt; t++) {
        cp_wait1();
        __syncthreads();

        if (t + 2 < nkt) load_tile((t + 2) % 3, (t + 2) << 4);
        else cp_commit();

        const unsigned* S  = smu + (t % 3) * STG_U32;
        const unsigned* SB = S + PL_U32;

        unsigned ah[4][4];
        #pragma unroll
        for (int im = 0; im < 4; im++) {
            int rb = (wm * 64 + im * 16 + gid) * 12 + tig;
            ah[im][0] = S[rb];      ah[im][1] = S[rb + 96];
            ah[im][2] = S[rb + 4];  ah[im][3] = S[rb + 100];
        }
        #pragma unroll
        for (int jn = 0; jn < 8; jn++) {
            int nb = (wn * 64 + jn * 8 + gid) * 12 + tig;
            unsigned b0 = SB[nb], b1 = SB[nb + 4];
            #pragma unroll
            for (int im = 0; im < 4; im++) {
                asm volatile(
                    "mma.sync.aligned.m16n8k16.row.col.f32.f16.f16.f32 "
                    "{%0,%1,%2,%3}, {%4,%5,%6,%7}, {%8,%9}, {%0,%1,%2,%3};"
                    : "+f"(acc[im][jn][0]), "+f"(acc[im][jn][1]),
                      "+f"(acc[im][jn][2]), "+f"(acc[im][jn][3])
                    : "r"(ah[im][0]), "r"(ah[im][1]), "r"(ah[im][2]), "r"(ah[im][3]),
                      "r"(b0), "r"(b1));
            }
        }
    }

    // epilogue
    #pragma unroll
    for (int im = 0; im < 4; im++) {
        #pragma unroll
        for (int jn = 0; jn < 8; jn++) {
            int col = col0 + wn * 64 + jn * 8 + tig * 2;
            if (col >= N) continue;
            float b0 = bias[col], b1 = bias[col + 1];
            int r0 = row0 + wm * 64 + im * 16 + gid;
            float v0 = acc[im][jn][0] + b0;
            float v1 = acc[im][jn][1] + b1;
            float v2 = acc[im][jn][2] + b0;
            float v3 = acc[im][jn][3] + b1;
            if (MODE == 1) {
                v0 = 0.5f*v0*(1.f + erff(v0*0.70710678118654752f));
                v1 = 0.5f*v1*(1.f + erff(v1*0.70710678118654752f));
                v2 = 0.5f*v2*(1.f + erff(v2*0.70710678118654752f));
                v3 = 0.5f*v3*(1.f + erff(v3*0.70710678118654752f));
            }
            if (MODE == 0 || MODE == 2) {
                *reinterpret_cast<float2*>(&C[(size_t)r0 * N + col]) = make_float2(v0, v1);
                *reinterpret_cast<float2*>(&C[(size_t)(r0+8) * N + col]) = make_float2(v2, v3);
            }
            if (MODE == 1 || MODE == 2) {
                __half2 h01; h01.x = __float2half_rn(v0); h01.y = __float2half_rn(v1);
                __half2 h23; h23.x = __float2half_rn(v2); h23.y = __float2half_rn(v3);
                *reinterpret_cast<__half2*>(&Ch[(size_t)r0 * N + col]) = h01;
                *reinterpret_cast<__half2*>(&Ch[(size_t)(r0+8) * N + col]) = h23;
            }
        }
    }
}

// ---------------- preprocessing: fp32 -> fp16 --------------------------------
__global__ void cvt_kernel(const float* __restrict__ src,
                           __half* __restrict__ dst, int n2)
{
    int i = blockIdx.x * blockDim.x + threadIdx.x;
    if (i < n2) {
        float2 v = reinterpret_cast<const float2*>(src)[i];
        __half2 h; h.x = __float2half_rn(v.x); h.y = __float2half_rn(v.y);
        reinterpret_cast<__half2*>(dst)[i] = h;
    }
}

// weight convert + transpose: W[K][N] fp32 -> [N][K] fp16
__global__ void wcvt_kernel(const float* __restrict__ W,
                            __half* __restrict__ H, int K, int N)
{
    int idx = blockIdx.x * blockDim.x + threadIdx.x;
    if (idx < N * K) {
        int n = idx / K, k = idx % K;
        H[idx] = __float2half_rn(W[(size_t)k * N + n]);
    }
}

// ---------------- conv v2: channel-major, rolling window --------------------
#define CTOK 32
__global__ void __launch_bounds__(128)
conv_kernel(const float* __restrict__ z,
            const float* __restrict__ convw,
            const float* __restrict__ convb,
            const float* __restrict__ dtb,
            const float* __restrict__ Alog,
            float* __restrict__ xbc,
            float* __restrict__ dtO,
            float* __restrict__ dAO)
{
    int c = blockIdx.x * 128 + threadIdx.x;
    int tok0 = blockIdx.y * CTOK;
    int l0 = tok0 & (SEQ - 1);

    if (c < CONV_DIM) {
        float w0 = convw[c*KCONV + 0];
        float w1 = convw[c*KCONV + 1];
        float w2 = convw[c*KCONV + 2];
        float w3 = convw[c*KCONV + 3];
        float bv = convb[c];
        const float* zp = z + (size_t)tok0 * D_IN_PROJ + D_INNER + c;
        float xm3 = (l0 > 0) ? zp[-3 * D_IN_PROJ] : 0.f;
        float xm2 = (l0 > 0) ? zp[-2 * D_IN_PROJ] : 0.f;
        float xm1 = (l0 > 0) ? zp[-1 * D_IN_PROJ] : 0.f;
        float* xp = xbc + (size_t)tok0 * CONV_DIM + c;
        #pragma unroll 4
        for (int t = 0; t < CTOK; t++) {
            float x0 = zp[(size_t)t * D_IN_PROJ];
            float acc = bv;
            acc = fmaf(w0, xm3, acc);
            acc = fmaf(w1, xm2, acc);
            acc = fmaf(w2, xm1, acc);
            acc = fmaf(w3, x0,  acc);
            xp[(size_t)t * CONV_DIM] = siluf(acc);
            xm3 = xm2; xm2 = xm1; xm1 = x0;
        }
    } else if (c < CONV_DIM + NHEADS) {
        int hh = c - CONV_DIM;
        float db = dtb[hh];
        float nA = -expf(Alog[hh]);
        const float* zp = z + (size_t)tok0 * D_IN_PROJ + 2*D_INNER + 2*D_STATE + hh;
        #pragma unroll 4
        for (int t = 0; t < CTOK; t++) {
            float v = zp[(size_t)t * D_IN_PROJ] + db;
            float sp = (v > 20.f) ? v : log1pf(expf(v));
            int tok = tok0 + t;
            dtO[tok*NHEADS + hh] = sp;
            dAO[tok*NHEADS + hh] = expf(nA * sp);
        }
    }
}

// ---------------- chunked selective scan: pass 1 ----------------------------
#define TT 32
__global__ void __launch_bounds__(128)
scan_local_kernel(const float* __restrict__ xbc, const float* __restrict__ dt,
                  const float* __restrict__ dA, const float* __restrict__ Dv,
                  float* __restrict__ y, float* __restrict__ cumO,
                  float* __restrict__ F)
{
    int hI = blockIdx.x;
    int b  = blockIdx.y;
    int ch = blockIdx.z;
    int lane = threadIdx.x & 31;
    int w    = threadIdx.x >> 5;
    float Dh = Dv[hI];

    float hs[8];
    #pragma unroll
    for (int i = 0; i < 8; i++) hs[i] = 0.f;
    float cum = 1.f;

    __shared__ float sB[TT][32];
    __shared__ float sC[TT][32];
    __shared__ float sxh[TT][32];
    __shared__ float sdt[TT];
    __shared__ float sdA[TT];
    __shared__ float scum[TT];
    __shared__ float ypart[4][TT][32];

    int tchunk0 = b * SEQ + ch * CHUNK;

    for (int tile = 0; tile < CHUNK / TT; tile++) {
        int t0 = tchunk0 + tile * TT;
        for (int j = threadIdx.x; j < TT * 32; j += 128) {
            int tl = j >> 5, c = j & 31;
            int tok = t0 + tl;
            const float* row = xbc + (size_t)tok * CONV_DIM;
            sB[tl][c] = row[D_INNER + c];
            sC[tl][c] = row[D_INNER + D_STATE + c];
            sxh[tl][c] = row[hI * HEADDIM + c];
        }
        if (threadIdx.x < TT) {
            sdt[threadIdx.x] = dt[(t0 + threadIdx.x) * NHEADS + hI];
            sdA[threadIdx.x] = dA[(t0 + threadIdx.x) * NHEADS + hI];
        }
        __syncthreads();

        for (int tl = 0; tl < TT; tl++) {
            float a  = sdA[tl];
            cum *= a;
            float dx = sdt[tl] * sxh[tl][lane];
            float4 b0 = *reinterpret_cast<const float4*>(&sB[tl][w * 8]);
            float4 b1 = *reinterpret_cast<const float4*>(&sB[tl][w * 8 + 4]);
            float4 c0 = *reinterpret_cast<const float4*>(&sC[tl][w * 8]);
            float4 c1 = *reinterpret_cast<const float4*>(&sC[tl][w * 8 + 4]);
            float bb[8] = {b0.x, b0.y, b0.z, b0.w, b1.x, b1.y, b1.z, b1.w};
            float cc[8] = {c0.x, c0.y, c0.z, c0.w, c1.x, c1.y, c1.z, c1.w};
            float acc = 0.f;
            #pragma unroll
            for (int i = 0; i < 8; i++) {
                hs[i] = fmaf(hs[i], a, dx * bb[i]);
                acc   = fmaf(hs[i], cc[i], acc);
            }
            ypart[w][tl][lane] = acc;
            if (threadIdx.x == 0) scum[tl] = cum;
        }
        __syncthreads();

        for (int j = threadIdx.x; j < TT * 32; j += 128) {
            int tl = j >> 5, p = j & 31;
            int tok = t0 + tl;
            float yv = ypart[0][tl][p] + ypart[1][tl][p] +
                       ypart[2][tl][p] + ypart[3][tl][p] + Dh * sxh[tl][p];
            y[(size_t)tok * D_INNER + hI * HEADDIM + p] = yv;
            if (p == 0) cumO[tok * NHEADS + hI] = scum[tl];
        }
        __syncthreads();
    }

    size_t fbase = (size_t)(((b * NHEADS + hI) * NCH + ch)) * 1024;
    #pragma unroll
    for (int i = 0; i < 8; i++) {
        int n = w * 8 + i;
        F[fbase + n * 32 + lane] = hs[i];
    }
}

// ---------------- pass 2: combine chunk states -----------------------------
__global__ void __launch_bounds__(256)
scan_combine_kernel(const float* __restrict__ F, const float* __restrict__ cum,
                    float* __restrict__ Hin)
{
    int hI = blockIdx.x, b = blockIdx.y;
    size_t base = (size_t)((b * NHEADS + hI) * NCH) * 1024;
    int off = threadIdx.x * 4;
    float4 hr = make_float4(0.f, 0.f, 0.f, 0.f);
    for (int c = 0; c < NCH; c++) {
        *reinterpret_cast<float4*>(&Hin[base + (size_t)c * 1024 + off]) = hr;
        float P = cum[(size_t)(b * SEQ + c * CHUNK + CHUNK - 1) * NHEADS + hI];
        float4 f = *reinterpret_cast<const float4*>(&F[base + (size_t)c * 1024 + off]);
        hr.x = fmaf(hr.x, P, f.x);
        hr.y = fmaf(hr.y, P, f.y);
        hr.z = fmaf(hr.z, P, f.z);
        hr.w = fmaf(hr.w, P, f.w);
    }
}

// ---------------- pass 3: apply chunk-initial-state correction -------------
__global__ void __launch_bounds__(128)
scan_fix_kernel(const float* __restrict__ xbc, const float* __restrict__ cum,
                const float* __restrict__ Hin, float* __restrict__ y)
{
    int hI = blockIdx.x, b = blockIdx.y, ch = blockIdx.z;
    if (ch == 0) return;
    int lane = threadIdx.x & 31, w = threadIdx.x >> 5;

    __shared__ float sh[32][32];
    size_t base = (size_t)(((b * NHEADS + hI) * NCH + ch)) * 1024;
    for (int j = threadIdx.x; j < 1024; j += 128)
        sh[j >> 5][j & 31] = Hin[base + j];
    __syncthreads();

    int t0 = b * SEQ + ch * CHUNK + w * 32;
    for (int tt = 0; tt < 32; tt++) {
        int tok = t0 + tt;
        float cv = xbc[(size_t)tok * CONV_DIM + D_INNER + D_STATE + lane];
        float pt = cum[tok * NHEADS + hI];
        float a0 = 0.f, a1 = 0.f;
        #pragma unroll
        for (int n = 0; n < 32; n += 2) {
            a0 = fmaf(__shfl_sync(0xffffffffu, cv, n),     sh[n][lane],     a0);
            a1 = fmaf(__shfl_sync(0xffffffffu, cv, n + 1), sh[n + 1][lane], a1);
        }
        y[(size_t)tok * D_INNER + hI * HEADDIM + lane] += pt * (a0 + a1);
    }
}

// ---------------- gated RMSNorm -> fp16 --------------------------------------
__global__ void __launch_bounds__(256)
gatednorm_kernel(const float* __restrict__ y, const float* __restrict__ zx,
                 const float* __restrict__ nw, __half* __restrict__ yh)
{
    int tok = blockIdx.x;
    int c0 = threadIdx.x * 2;
    float v0, v1, ss;
    {
        float z0 = zx[(size_t)tok * D_IN_PROJ + c0];
        float z1 = zx[(size_t)tok * D_IN_PROJ + c0 + 1];
        v0 = y[(size_t)tok * D_INNER + c0]     * siluf(z0);
        v1 = y[(size_t)tok * D_INNER + c0 + 1] * siluf(z1);
        ss = v0 * v0 + v1 * v1;
    }
    ss = blockSum(ss);
    float scale = rsqrtf(ss / (float)D_INNER + EPS);
    __half2 h;
    h.x = __float2half_rn(v0 * scale * nw[c0]);
    h.y = __float2half_rn(v1 * scale * nw[c0 + 1]);
    *reinterpret_cast<__half2*>(&yh[(size_t)tok * D_INNER + c0]) = h;
}

// ---------------- residual + RMSNorm (+ optional fused LayerNorm) -----------
// DOLN=0: act = rmsnorm(o+act, wgt); acth = fp16(act).
// DOLN=1: lnh = fp16(layernorm(rmsnorm(o+act, wgt), lnw, lnb))
template<int DOLN>
__global__ void __launch_bounds__(256)
resnorm_kernel(const float* __restrict__ o, float* __restrict__ act,
               const float* __restrict__ wgt,
               __half* __restrict__ acth,
               const float* __restrict__ lnw, const float* __restrict__ lnb,
               __half* __restrict__ lnh)
{
    int tok = blockIdx.x, c = threadIdx.x;
    float v = o[(size_t)tok * HIDDEN + c] + act[(size_t)tok * HIDDEN + c];
    float ss = blockSum(v * v);
    float r = v * rsqrtf(ss / (float)HIDDEN + EPS) * wgt[c];
    if (DOLN == 0) {
        act[(size_t)tok * HIDDEN + c] = r;
        acth[(size_t)tok * HIDDEN + c] = __float2half_rn(r);
    } else {
        float s  = blockSum(r);
        float s2 = blockSum(r * r);
        float m = s / (float)HIDDEN;
        float var = s2 / (float)HIDDEN - m * m;
        float ln = (r - m) * rsqrtf(var + EPS) * lnw[c] + lnb[c];
        lnh[(size_t)tok * HIDDEN + c] = __float2half_rn(ln);
    }
}

// ---------------- LayerNorm (final) -----------------------------------------
__global__ void __launch_bounds__(256)
layernorm_kernel(const float* __restrict__ in, const float* __restrict__ w,
                 const float* __restrict__ bsl, float* __restrict__ out)
{
    int tok = blockIdx.x, c = threadIdx.x;
    float v = in[(size_t)tok * HIDDEN + c];
    float s  = blockSum(v);
    float s2 = blockSum(v * v);
    float m = s / (float)HIDDEN;
    float var = s2 / (float)HIDDEN - m * m;
    out[(size_t)tok * HIDDEN + c] = (v - m) * rsqrtf(var + EPS) * w[c] + bsl[c];
}

// ---------------- launch ----------------------------------------------------
extern "C" void kernel_launch(void* const* d_in, const int* in_sizes, int n_in,
                              void* d_out, int out_size)
{
    const float* x      = (const float*)d_in[0];
    const float* ip_w   = (const float*)d_in[1];
    const float* ip_b   = (const float*)d_in[2];
    const float* m_inw  = (const float*)d_in[3];
    const float* m_inb  = (const float*)d_in[4];
    const float* m_convw= (const float*)d_in[5];
    const float* m_convb= (const float*)d_in[6];
    const float* m_dtb  = (const float*)d_in[7];
    const float* m_Alog = (const float*)d_in[8];
    const float* m_D    = (const float*)d_in[9];
    const float* m_nw   = (const float*)d_in[10];
    const float* m_outw = (const float*)d_in[11];
    const float* m_outb = (const float*)d_in[12];
    const float* rms_w  = (const float*)d_in[13];
    const float* ln1_w  = (const float*)d_in[14];
    const float* ln1_b  = (const float*)d_in[15];
    const float* w1     = (const float*)d_in[16];
    const float* b1     = (const float*)d_in[17];
    const float* w2     = (const float*)d_in[18];
    const float* b2     = (const float*)d_in[19];
    const float* ln2_w  = (const float*)d_in[20];
    const float* ln2_b  = (const float*)d_in[21];
    float* out = (float*)d_out;

    float *act, *z, *xbc, *dt, *dA, *y, *o, *cum, *F, *Hin;
    __half *xh, *acth, *yh, *lh, *wh;
    cudaGetSymbolAddress((void**)&act, g_act);
    cudaGetSymbolAddress((void**)&z,   g_z);
    cudaGetSymbolAddress((void**)&xbc, g_xbc);
    cudaGetSymbolAddress((void**)&dt,  g_dt);
    cudaGetSymbolAddress((void**)&dA,  g_dA);
    cudaGetSymbolAddress((void**)&y,   g_y);
    cudaGetSymbolAddress((void**)&o,   g_o);
    cudaGetSymbolAddress((void**)&cum, g_cum);
    cudaGetSymbolAddress((void**)&F,   g_F);
    cudaGetSymbolAddress((void**)&Hin, g_Hin);
    cudaGetSymbolAddress((void**)&xh,   g_xh);
    cudaGetSymbolAddress((void**)&acth, g_acth);
    cudaGetSymbolAddress((void**)&yh,   g_yh);
    cudaGetSymbolAddress((void**)&lh,   g_lh);
    cudaGetSymbolAddress((void**)&wh,   g_wh);

    cudaFuncSetAttribute(hgemm_kernel<0>, cudaFuncAttributeMaxDynamicSharedMemorySize, SMB_GEMM);
    cudaFuncSetAttribute(hgemm_kernel<1>, cudaFuncAttributeMaxDynamicSharedMemorySize, SMB_GEMM);
    cudaFuncSetAttribute(hgemm_kernel<2>, cudaFuncAttributeMaxDynamicSharedMemorySize, SMB_GEMM);

    // ---- preprocessing: convert x + weights (transpose W to [N][K]) ----
    {
        int n2 = NTOK * INPUT_DIM / 2;
        cvt_kernel<<<(n2 + 255) / 256, 256>>>(x, xh, n2);
        int n;
        n = 256 * 1024;
        wcvt_kernel<<<(n + 255) / 256, 256>>>(ip_w, wh + OFF_IPW, 1024, 256);
        n = 1104 * 256;
        wcvt_kernel<<<(n + 255) / 256, 256>>>(m_inw, wh + OFF_INW, 256, 1104);
        wcvt_kernel<<<(n + 255) / 256, 256>>>(m_inw + 256 * 1104,
            wh + OFF_INW + 1104 * 256, 256, 1104);
        n = 256 * 512;
        wcvt_kernel<<<(n + 255) / 256, 256>>>(m_outw, wh + OFF_OUTW, 512, 256);
        wcvt_kernel<<<(n + 255) / 256, 256>>>(m_outw + 512 * 256,
            wh + OFF_OUTW + 256 * 512, 512, 256);
        n = 512 * 256;
        wcvt_kernel<<<(n + 255) / 256, 256>>>(w1, wh + OFF_W1, 256, 512);
        wcvt_kernel<<<(n + 255) / 256, 256>>>(w2, wh + OFF_W2, 512, 256);
    }

    const int MB = NTOK / 128;   // 256 row-blocks

    // input projection: act fp32 + acth fp16
    hgemm_kernel<2><<<dim3(2, MB), 128, SMB_GEMM>>>(xh, wh + OFF_IPW, ip_b,
        act, acth, NTOK, HIDDEN, INPUT_DIM);

    for (int i = 0; i < 2; i++) {
        hgemm_kernel<0><<<dim3(9, MB), 128, SMB_GEMM>>>(acth,
            wh + OFF_INW + (size_t)i * 1104 * 256, m_inb + i * D_IN_PROJ,
            z, (__half*)nullptr, NTOK, D_IN_PROJ, HIDDEN);
        conv_kernel<<<dim3(5, NTOK / CTOK), 128>>>(
            z, m_convw + (size_t)i * CONV_DIM * KCONV,
            m_convb + i * CONV_DIM, m_dtb + i * NHEADS,
            m_Alog + i * NHEADS, xbc, dt, dA);
        scan_local_kernel<<<dim3(NHEADS, BATCH, NCH), 128>>>(
            xbc, dt, dA, m_D + i * NHEADS, y, cum, F);
        scan_combine_kernel<<<dim3(NHEADS, BATCH), 256>>>(F, cum, Hin);
        scan_fix_kernel<<<dim3(NHEADS, BATCH, NCH), 128>>>(xbc, cum, Hin, y);
        gatednorm_kernel<<<NTOK, 256>>>(y, z, m_nw + i * D_INNER, yh);
        hgemm_kernel<0><<<dim3(2, MB), 128, SMB_GEMM>>>(yh,
            wh + OFF_OUTW + (size_t)i * 256 * 512, m_outb + i * HIDDEN,
            o, (__half*)nullptr, NTOK, HIDDEN, D_INNER);
        if (i == 0)
            resnorm_kernel<0><<<NTOK, 256>>>(o, act, rms_w + i * HIDDEN, acth,
                                             (const float*)nullptr, (const float*)nullptr,
                                             (__half*)nullptr);
        else
            resnorm_kernel<1><<<NTOK, 256>>>(o, act, rms_w + i * HIDDEN,
                                             (__half*)nullptr, ln1_w, ln1_b, lh);
    }

    // MLP head
    hgemm_kernel<1><<<dim3(4, MB), 128, SMB_GEMM>>>(lh, wh + OFF_W1, b1,
        (float*)nullptr, yh, NTOK, 2 * HIDDEN, HIDDEN);   // gelu -> fp16
    hgemm_kernel<0><<<dim3(2, MB), 128, SMB_GEMM>>>(yh, wh + OFF_W2, b2,
        o, (__half*)nullptr, NTOK, HIDDEN, 2 * HIDDEN);
    layernorm_kernel<<<NTOK, 256>>>(o, ln2_w, ln2_b, out);
}